// round 1
// baseline (speedup 1.0000x reference)
#include <cuda_runtime.h>

#define E_TOTAL 300000
#define TILE_M  128

// ---- shared memory layout (float offsets) ----
#define LDA   20     // As staging leading dim (128 x 16 tile) -> conflict-free frags
#define LDB1  136    // Bs staging (16 x 128)
#define LDH   132    // H1 buffer (128 x 128)
#define LDB2  184    // Bs2 staging (16 x 176)
#define LDS2  184    // S2 buffer (128 x 176)
#define LDWO  136    // wo (16 x 128)
#define LDY   20     // Y (128 x 16)

#define H1_OFF   0                  // 128*132 = 16896
#define AS_OFF   16896              // 2*128*20 = 5120
#define BS1_OFF  22016              // 2*16*136 = 4352 (end 26368)
#define BS2_OFF  16896              // 2*16*184 = 5888 (reuses As region, GEMM2 only)
#define S2_OFF   0                  // 128*184 = 23552 (overlays H1s+staging, after sync)
#define YS_OFF   26368              // 128*20 = 2560
#define WOS_OFF  28928              // 16*136 = 2176
#define B1_OFF   31104              // 128
#define B2E_OFF  31232              // 176
#define BO_OFF   31408              // 128
#define SMEM_FLOATS 31536
#define SMEM_BYTES (SMEM_FLOATS * 4)

// fused second-layer weights: [w2 | w2@wg | w2@wt | w2@wp]  (128 x 176)
__device__ float g_w2ext[128 * 176];
__device__ float g_b2ext[176];

__device__ __forceinline__ float f2tf(float x) {
    unsigned u;
    asm("cvt.rna.tf32.f32 %0, %1;" : "=r"(u) : "f"(x));
    return __uint_as_float(u);
}

__device__ __forceinline__ void mma8(float* c, const unsigned* a, const unsigned* b) {
    asm volatile(
        "mma.sync.aligned.m16n8k8.row.col.f32.tf32.tf32.f32 "
        "{%0,%1,%2,%3}, {%4,%5,%6,%7}, {%8,%9}, {%0,%1,%2,%3};"
        : "+f"(c[0]), "+f"(c[1]), "+f"(c[2]), "+f"(c[3])
        : "r"(a[0]), "r"(a[1]), "r"(a[2]), "r"(a[3]), "r"(b[0]), "r"(b[1]));
}

// ---- prep: W2ext / b2ext  (tiny; runs once per launch) ----
__global__ void prep_kernel(const float* __restrict__ w2, const float* __restrict__ b2,
                            const float* __restrict__ wg, const float* __restrict__ bg,
                            const float* __restrict__ wt, const float* __restrict__ bt,
                            const float* __restrict__ wp, const float* __restrict__ bp) {
    int n = blockIdx.x;     // 0..175
    int k = threadIdx.x;    // 0..127
    if (n < 128) {
        g_w2ext[k * 176 + n] = w2[k * 128 + n];
        if (k == 0) g_b2ext[n] = b2[n];
    } else {
        int p = (n - 128) >> 4, j = (n - 128) & 15;
        const float* W = (p == 0) ? wg : (p == 1) ? wt : wp;
        const float* B = (p == 0) ? bg : (p == 1) ? bt : bp;
        float s = 0.f;
        for (int m = 0; m < 128; m++) s += w2[k * 128 + m] * W[m * 16 + j];
        g_w2ext[k * 176 + n] = s;
        if (k == 0) {
            float sb = B[j];
            for (int m = 0; m < 128; m++) sb += b2[m] * W[m * 16 + j];
            g_b2ext[n] = sb;
        }
    }
}

// ---- main fused kernel: 128 edges per CTA ----
extern __shared__ float sm[];

__global__ void __launch_bounds__(256, 1)
edge_att_kernel(const float* __restrict__ src, const float* __restrict__ tgt,
                const float* __restrict__ ea,
                const float* __restrict__ w1, const float* __restrict__ b1,
                const float* __restrict__ wo, const float* __restrict__ bo,
                float* __restrict__ out) {
    const int tid = threadIdx.x;
    const int lane = tid & 31;
    const int wid = tid >> 5;
    const int wm = wid & 3;          // 4 M-warps
    const int wn = wid >> 2;         // 2 N-warps
    const int row0 = wm * 32;
    const int col0 = wn * 64;
    const long e0 = (long)blockIdx.x * TILE_M;

    // persistent small tiles
    for (int idx = tid; idx < 2048; idx += 256) {
        int k = idx >> 7, n = idx & 127;
        sm[WOS_OFF + k * LDWO + n] = f2tf(wo[idx]);
    }
    if (tid < 128) sm[B1_OFF + tid] = b1[tid];
    if (tid < 128) sm[BO_OFF + tid] = bo[tid];
    if (tid < 176) sm[B2E_OFF + tid] = g_b2ext[tid];

    // ================= GEMM1: H1 = relu(X @ W1 + b1),  M128 N128 K384 =================
    float acc1[2][8][4];
#pragma unroll
    for (int mt = 0; mt < 2; mt++)
#pragma unroll
        for (int nt = 0; nt < 8; nt++)
#pragma unroll
            for (int q = 0; q < 4; q++) acc1[mt][nt][q] = 0.f;

    float4 pa[2], pb[2];

    auto ldgA1 = [&](int kc) {
        int kb = kc * 16, sel = kb >> 7, cin = kb & 127;
        const float* sp = (sel == 0) ? src : (sel == 1) ? tgt : ea;
#pragma unroll
        for (int i = 0; i < 2; i++) {
            int f = tid + i * 256, r = f >> 2, c4 = f & 3;
            long e = e0 + r; if (e >= E_TOTAL) e = E_TOTAL - 1;
            pa[i] = *(const float4*)(sp + e * 128 + cin + c4 * 4);
        }
    };
    auto ldgB1 = [&](int kc) {
        int kb = kc * 16;
#pragma unroll
        for (int i = 0; i < 2; i++) {
            int f = tid + i * 256, r = f >> 5, c4 = f & 31;
            pb[i] = *(const float4*)(w1 + (long)(kb + r) * 128 + c4 * 4);
        }
    };
    auto stsAB1 = [&](int buf) {
#pragma unroll
        for (int i = 0; i < 2; i++) {
            int f = tid + i * 256, r = f >> 2, c4 = f & 3;
            float4 v = pa[i];
            v.x = f2tf(v.x); v.y = f2tf(v.y); v.z = f2tf(v.z); v.w = f2tf(v.w);
            *(float4*)&sm[AS_OFF + buf * (128 * LDA) + r * LDA + c4 * 4] = v;
        }
#pragma unroll
        for (int i = 0; i < 2; i++) {
            int f = tid + i * 256, r = f >> 5, c4 = f & 31;
            float4 v = pb[i];
            v.x = f2tf(v.x); v.y = f2tf(v.y); v.z = f2tf(v.z); v.w = f2tf(v.w);
            *(float4*)&sm[BS1_OFF + buf * (16 * LDB1) + r * LDB1 + c4 * 4] = v;
        }
    };

    ldgA1(0); ldgB1(0); stsAB1(0);
    __syncthreads();

    for (int kc = 0; kc < 24; kc++) {
        int cur = kc & 1;
        if (kc + 1 < 24) { ldgA1(kc + 1); ldgB1(kc + 1); }
        const float* Ab = &sm[AS_OFF + cur * (128 * LDA)];
        const float* Bb = &sm[BS1_OFF + cur * (16 * LDB1)];
#pragma unroll
        for (int ks = 0; ks < 2; ks++) {
            unsigned a[2][4];
#pragma unroll
            for (int mt = 0; mt < 2; mt++) {
                int r = row0 + mt * 16 + (lane >> 2);
                int c = ks * 8 + (lane & 3);
                a[mt][0] = __float_as_uint(Ab[r * LDA + c]);
                a[mt][1] = __float_as_uint(Ab[(r + 8) * LDA + c]);
                a[mt][2] = __float_as_uint(Ab[r * LDA + c + 4]);
                a[mt][3] = __float_as_uint(Ab[(r + 8) * LDA + c + 4]);
            }
#pragma unroll
            for (int nt = 0; nt < 8; nt++) {
                int kk = ks * 8 + (lane & 3);
                int c = col0 + nt * 8 + (lane >> 2);
                unsigned b[2] = { __float_as_uint(Bb[kk * LDB1 + c]),
                                  __float_as_uint(Bb[(kk + 4) * LDB1 + c]) };
                mma8(acc1[0][nt], a[0], b);
                mma8(acc1[1][nt], a[1], b);
            }
        }
        if (kc + 1 < 24) stsAB1((kc + 1) & 1);
        __syncthreads();
    }

    // epilogue: +b1, relu, round to tf32, store H1 to smem
#pragma unroll
    for (int mt = 0; mt < 2; mt++)
#pragma unroll
        for (int nt = 0; nt < 8; nt++) {
            int r = row0 + mt * 16 + (lane >> 2);
            int c = col0 + nt * 8 + (lane & 3) * 2;
            float bb0 = sm[B1_OFF + c], bb1 = sm[B1_OFF + c + 1];
            float v0 = f2tf(fmaxf(acc1[mt][nt][0] + bb0, 0.f));
            float v1 = f2tf(fmaxf(acc1[mt][nt][1] + bb1, 0.f));
            float v2 = f2tf(fmaxf(acc1[mt][nt][2] + bb0, 0.f));
            float v3 = f2tf(fmaxf(acc1[mt][nt][3] + bb1, 0.f));
            *(float2*)&sm[H1_OFF + r * LDH + c] = make_float2(v0, v1);
            *(float2*)&sm[H1_OFF + (r + 8) * LDH + c] = make_float2(v2, v3);
        }
    __syncthreads();

    // ================= GEMM2: [H2|G|TH|PH] = H1 @ W2ext + b2ext,  M128 N176 K128 ======
    float acc2[2][11][4];
#pragma unroll
    for (int mt = 0; mt < 2; mt++)
#pragma unroll
        for (int nt = 0; nt < 11; nt++)
#pragma unroll
            for (int q = 0; q < 4; q++) acc2[mt][nt][q] = 0.f;

    float4 pc[3];
    auto ldgB2 = [&](int kc) {
        int kb = kc * 16;
#pragma unroll
        for (int i = 0; i < 3; i++) {
            int f = tid + i * 256;
            if (f < 704) {
                int r = f / 44, c4 = f % 44;
                pc[i] = *(const float4*)(g_w2ext + (kb + r) * 176 + c4 * 4);
            }
        }
    };
    auto stsB2 = [&](int buf) {
#pragma unroll
        for (int i = 0; i < 3; i++) {
            int f = tid + i * 256;
            if (f < 704) {
                int r = f / 44, c4 = f % 44;
                float4 v = pc[i];
                v.x = f2tf(v.x); v.y = f2tf(v.y); v.z = f2tf(v.z); v.w = f2tf(v.w);
                *(float4*)&sm[BS2_OFF + buf * (16 * LDB2) + r * LDB2 + c4 * 4] = v;
            }
        }
    };

    ldgB2(0); stsB2(0);
    __syncthreads();

    for (int kc = 0; kc < 8; kc++) {
        int cur = kc & 1;
        if (kc + 1 < 8) ldgB2(kc + 1);
        const float* Bb = &sm[BS2_OFF + cur * (16 * LDB2)];
#pragma unroll
        for (int ks = 0; ks < 2; ks++) {
            int kg = kc * 16 + ks * 8;
            unsigned a[2][4];
#pragma unroll
            for (int mt = 0; mt < 2; mt++) {
                int r = row0 + mt * 16 + (lane >> 2);
                int c = kg + (lane & 3);
                a[mt][0] = __float_as_uint(sm[H1_OFF + r * LDH + c]);
                a[mt][1] = __float_as_uint(sm[H1_OFF + (r + 8) * LDH + c]);
                a[mt][2] = __float_as_uint(sm[H1_OFF + r * LDH + c + 4]);
                a[mt][3] = __float_as_uint(sm[H1_OFF + (r + 8) * LDH + c + 4]);
            }
#pragma unroll
            for (int nt = 0; nt < 11; nt++) {
                int kk = ks * 8 + (lane & 3);
                int c = wn * 88 + nt * 8 + (lane >> 2);
                unsigned b[2] = { __float_as_uint(Bb[kk * LDB2 + c]),
                                  __float_as_uint(Bb[(kk + 4) * LDB2 + c]) };
                mma8(acc2[0][nt], a[0], b);
                mma8(acc2[1][nt], a[1], b);
            }
        }
        if (kc + 1 < 8) stsB2((kc + 1) & 1);
        __syncthreads();
    }
    // all H1/Bs2 reads done (loop-final sync) -> safe to overlay S2
#pragma unroll
    for (int mt = 0; mt < 2; mt++)
#pragma unroll
        for (int nt = 0; nt < 11; nt++) {
            int r = row0 + mt * 16 + (lane >> 2);
            int c = wn * 88 + nt * 8 + (lane & 3) * 2;
            float bb0 = sm[B2E_OFF + c], bb1 = sm[B2E_OFF + c + 1];
            *(float2*)&sm[S2_OFF + r * LDS2 + c] =
                make_float2(acc2[mt][nt][0] + bb0, acc2[mt][nt][1] + bb1);
            *(float2*)&sm[S2_OFF + (r + 8) * LDS2 + c] =
                make_float2(acc2[mt][nt][2] + bb0, acc2[mt][nt][3] + bb1);
        }
    __syncthreads();

    // ================= attention: Y[r][i] = softmax_j(ph_i*th_j) . g =================
    {
        int r = tid >> 1;
        int i0 = (tid & 1) * 8;
        const float* srow = &sm[S2_OFF + r * LDS2];
        float gg[16], th[16];
#pragma unroll
        for (int j = 0; j < 16; j++) { gg[j] = srow[128 + j]; th[j] = srow[144 + j]; }
#pragma unroll
        for (int i = i0; i < i0 + 8; i++) {
            float ph = srow[160 + i];
            float m = ph * th[0];
#pragma unroll
            for (int j = 1; j < 16; j++) m = fmaxf(m, ph * th[j]);
            float s = 0.f, ys = 0.f;
#pragma unroll
            for (int j = 0; j < 16; j++) {
                float e = __expf(ph * th[j] - m);
                s += e; ys += e * gg[j];
            }
            sm[YS_OFF + r * LDY + i] = f2tf(ys / s);
        }
    }
    __syncthreads();

    // ================= GEMM3: OUT = Y @ wo + bo + H2,  M128 N128 K16 =================
    float acc3[2][8][4];
#pragma unroll
    for (int mt = 0; mt < 2; mt++)
#pragma unroll
        for (int nt = 0; nt < 8; nt++)
#pragma unroll
            for (int q = 0; q < 4; q++) acc3[mt][nt][q] = 0.f;

#pragma unroll
    for (int ks = 0; ks < 2; ks++) {
        unsigned a[2][4];
#pragma unroll
        for (int mt = 0; mt < 2; mt++) {
            int r = row0 + mt * 16 + (lane >> 2);
            int c = ks * 8 + (lane & 3);
            a[mt][0] = __float_as_uint(sm[YS_OFF + r * LDY + c]);
            a[mt][1] = __float_as_uint(sm[YS_OFF + (r + 8) * LDY + c]);
            a[mt][2] = __float_as_uint(sm[YS_OFF + r * LDY + c + 4]);
            a[mt][3] = __float_as_uint(sm[YS_OFF + (r + 8) * LDY + c + 4]);
        }
#pragma unroll
        for (int nt = 0; nt < 8; nt++) {
            int kk = ks * 8 + (lane & 3);
            int c = col0 + nt * 8 + (lane >> 2);
            unsigned b[2] = { __float_as_uint(sm[WOS_OFF + kk * LDWO + c]),
                              __float_as_uint(sm[WOS_OFF + (kk + 4) * LDWO + c]) };
            mma8(acc3[0][nt], a[0], b);
            mma8(acc3[1][nt], a[1], b);
        }
    }

#pragma unroll
    for (int mt = 0; mt < 2; mt++)
#pragma unroll
        for (int nt = 0; nt < 8; nt++) {
            int r = row0 + mt * 16 + (lane >> 2);
            int c = col0 + nt * 8 + (lane & 3) * 2;
            float bb0 = sm[BO_OFF + c], bb1 = sm[BO_OFF + c + 1];
            long e = e0 + r;
            if (e < E_TOTAL) {
                float o0 = acc3[mt][nt][0] + sm[S2_OFF + r * LDS2 + c] + bb0;
                float o1 = acc3[mt][nt][1] + sm[S2_OFF + r * LDS2 + c + 1] + bb1;
                *(float2*)&out[e * 128 + c] = make_float2(o0, o1);
            }
            long e2 = e + 8;
            if (e2 < E_TOTAL) {
                float o2 = acc3[mt][nt][2] + sm[S2_OFF + (r + 8) * LDS2 + c] + bb0;
                float o3 = acc3[mt][nt][3] + sm[S2_OFF + (r + 8) * LDS2 + c + 1] + bb1;
                *(float2*)&out[e2 * 128 + c] = make_float2(o2, o3);
            }
        }
}

extern "C" void kernel_launch(void* const* d_in, const int* in_sizes, int n_in,
                              void* d_out, int out_size) {
    const float* src = (const float*)d_in[0];
    const float* tgt = (const float*)d_in[1];
    const float* ea  = (const float*)d_in[2];
    const float* w1  = (const float*)d_in[3];
    const float* b1  = (const float*)d_in[4];
    const float* w2  = (const float*)d_in[5];
    const float* b2  = (const float*)d_in[6];
    const float* wg  = (const float*)d_in[7];
    const float* bg  = (const float*)d_in[8];
    const float* wt  = (const float*)d_in[9];
    const float* bt  = (const float*)d_in[10];
    const float* wp  = (const float*)d_in[11];
    const float* bp  = (const float*)d_in[12];
    const float* wo  = (const float*)d_in[13];
    const float* bo  = (const float*)d_in[14];
    float* out = (float*)d_out;

    cudaFuncSetAttribute(edge_att_kernel,
                         cudaFuncAttributeMaxDynamicSharedMemorySize, SMEM_BYTES);

    prep_kernel<<<176, 128>>>(w2, b2, wg, bg, wt, bt, wp, bp);

    int grid = (E_TOTAL + TILE_M - 1) / TILE_M;  // 2344
    edge_att_kernel<<<grid, 256, SMEM_BYTES>>>(src, tgt, ea, w1, b1, wo, bo, out);
}

// round 2
// speedup vs baseline: 1.0157x; 1.0157x over previous
#include <cuda_runtime.h>

#define E_TOTAL 300000
#define TILE_M  128
#define NTHREADS 512

// ---- shared memory layout (float offsets) ----
#define LDA   20     // As staging leading dim (128 x 16 tile) -> conflict-free frags
#define LDB1  136    // Bs staging (16 x 128)
#define LDH   132    // H1 buffer (128 x 128)
#define LDB2  184    // Bs2 staging (16 x 176)
#define LDS2  184    // S2 buffer (128 x 176)
#define LDWO  136    // wo (16 x 128)
#define LDY   20     // Y (128 x 16)

#define H1_OFF   0                  // 128*132 = 16896
#define AS_OFF   16896              // 2*128*20 = 5120
#define BS1_OFF  22016              // 2*16*136 = 4352 (end 26368)
#define BS2_OFF  16896              // 2*16*184 = 5888 (reuses As region, GEMM2 only)
#define S2_OFF   0                  // 128*184 = 23552 (overlays H1s+staging, after sync)
#define YS_OFF   26368              // 128*20 = 2560
#define WOS_OFF  28928              // 16*136 = 2176
#define B1_OFF   31104              // 128
#define B2E_OFF  31232              // 176
#define BO_OFF   31408              // 128
#define SMEM_FLOATS 31536
#define SMEM_BYTES (SMEM_FLOATS * 4)

// fused second-layer weights: [w2 | w2@wg | w2@wt | w2@wp]  (128 x 176)
__device__ float g_w2ext[128 * 176];
__device__ float g_b2ext[176];

__device__ __forceinline__ float f2tf(float x) {
    unsigned u;
    asm("cvt.rna.tf32.f32 %0, %1;" : "=r"(u) : "f"(x));
    return __uint_as_float(u);
}

__device__ __forceinline__ void mma8(float* c, const unsigned* a, const unsigned* b) {
    asm volatile(
        "mma.sync.aligned.m16n8k8.row.col.f32.tf32.tf32.f32 "
        "{%0,%1,%2,%3}, {%4,%5,%6,%7}, {%8,%9}, {%0,%1,%2,%3};"
        : "+f"(c[0]), "+f"(c[1]), "+f"(c[2]), "+f"(c[3])
        : "r"(a[0]), "r"(a[1]), "r"(a[2]), "r"(a[3]), "r"(b[0]), "r"(b[1]));
}

// ---- prep: W2ext / b2ext  (tiny; runs once per launch) ----
__global__ void prep_kernel(const float* __restrict__ w2, const float* __restrict__ b2,
                            const float* __restrict__ wg, const float* __restrict__ bg,
                            const float* __restrict__ wt, const float* __restrict__ bt,
                            const float* __restrict__ wp, const float* __restrict__ bp) {
    int n = blockIdx.x;     // 0..175
    int k = threadIdx.x;    // 0..127
    if (n < 128) {
        g_w2ext[k * 176 + n] = w2[k * 128 + n];
        if (k == 0) g_b2ext[n] = b2[n];
    } else {
        int p = (n - 128) >> 4, j = (n - 128) & 15;
        const float* W = (p == 0) ? wg : (p == 1) ? wt : wp;
        const float* B = (p == 0) ? bg : (p == 1) ? bt : bp;
        float s = 0.f;
        for (int m = 0; m < 128; m++) s += w2[k * 128 + m] * W[m * 16 + j];
        g_w2ext[k * 176 + n] = s;
        if (k == 0) {
            float sb = B[j];
            for (int m = 0; m < 128; m++) sb += b2[m] * W[m * 16 + j];
            g_b2ext[n] = sb;
        }
    }
}

// ---- main fused kernel: 128 edges per CTA, 512 threads (16 warps, 8M x 2N) ----
extern __shared__ float sm[];

__global__ void __launch_bounds__(NTHREADS, 1)
edge_att_kernel(const float* __restrict__ src, const float* __restrict__ tgt,
                const float* __restrict__ ea,
                const float* __restrict__ w1, const float* __restrict__ b1,
                const float* __restrict__ wo, const float* __restrict__ bo,
                float* __restrict__ out) {
    const int tid = threadIdx.x;
    const int lane = tid & 31;
    const int wid = tid >> 5;
    const int wm = wid & 7;          // 8 M-warps (16 rows each)
    const int wn = wid >> 3;         // 2 N-warps
    const int row0 = wm * 16;
    const int col0 = wn * 64;
    const long e0 = (long)blockIdx.x * TILE_M;

    // persistent small tiles
    for (int idx = tid; idx < 2048; idx += NTHREADS) {
        int k = idx >> 7, n = idx & 127;
        sm[WOS_OFF + k * LDWO + n] = f2tf(wo[idx]);
    }
    if (tid < 128) sm[B1_OFF + tid] = b1[tid];
    if (tid < 128) sm[BO_OFF + tid] = bo[tid];
    if (tid < 176) sm[B2E_OFF + tid] = g_b2ext[tid];

    // ================= GEMM1: H1 = relu(X @ W1 + b1),  M128 N128 K384 =================
    float acc1[8][4];
#pragma unroll
    for (int nt = 0; nt < 8; nt++)
#pragma unroll
        for (int q = 0; q < 4; q++) acc1[nt][q] = 0.f;

    float4 pa, pb;

    auto ldgA1 = [&](int kc) {
        int kb = kc * 16, sel = kb >> 7, cin = kb & 127;
        const float* sp = (sel == 0) ? src : (sel == 1) ? tgt : ea;
        int r = tid >> 2, c4 = tid & 3;
        long e = e0 + r; if (e >= E_TOTAL) e = E_TOTAL - 1;
        pa = *(const float4*)(sp + e * 128 + cin + c4 * 4);
    };
    auto ldgB1 = [&](int kc) {
        int kb = kc * 16;
        int r = tid >> 5, c4 = tid & 31;
        pb = *(const float4*)(w1 + (long)(kb + r) * 128 + c4 * 4);
    };
    auto stsAB1 = [&](int buf) {
        {
            int r = tid >> 2, c4 = tid & 3;
            float4 v = pa;
            v.x = f2tf(v.x); v.y = f2tf(v.y); v.z = f2tf(v.z); v.w = f2tf(v.w);
            *(float4*)&sm[AS_OFF + buf * (128 * LDA) + r * LDA + c4 * 4] = v;
        }
        {
            int r = tid >> 5, c4 = tid & 31;
            float4 v = pb;
            v.x = f2tf(v.x); v.y = f2tf(v.y); v.z = f2tf(v.z); v.w = f2tf(v.w);
            *(float4*)&sm[BS1_OFF + buf * (16 * LDB1) + r * LDB1 + c4 * 4] = v;
        }
    };

    ldgA1(0); ldgB1(0); stsAB1(0);
    __syncthreads();

    for (int kc = 0; kc < 24; kc++) {
        int cur = kc & 1;
        if (kc + 1 < 24) { ldgA1(kc + 1); ldgB1(kc + 1); }
        const float* Ab = &sm[AS_OFF + cur * (128 * LDA)];
        const float* Bb = &sm[BS1_OFF + cur * (16 * LDB1)];
#pragma unroll
        for (int ks = 0; ks < 2; ks++) {
            unsigned a[4];
            {
                int r = row0 + (lane >> 2);
                int c = ks * 8 + (lane & 3);
                a[0] = __float_as_uint(Ab[r * LDA + c]);
                a[1] = __float_as_uint(Ab[(r + 8) * LDA + c]);
                a[2] = __float_as_uint(Ab[r * LDA + c + 4]);
                a[3] = __float_as_uint(Ab[(r + 8) * LDA + c + 4]);
            }
#pragma unroll
            for (int nt = 0; nt < 8; nt++) {
                int kk = ks * 8 + (lane & 3);
                int c = col0 + nt * 8 + (lane >> 2);
                unsigned b[2] = { __float_as_uint(Bb[kk * LDB1 + c]),
                                  __float_as_uint(Bb[(kk + 4) * LDB1 + c]) };
                mma8(acc1[nt], a, b);
            }
        }
        if (kc + 1 < 24) stsAB1((kc + 1) & 1);
        __syncthreads();
    }

    // epilogue: +b1, relu, round to tf32, store H1 to smem
#pragma unroll
    for (int nt = 0; nt < 8; nt++) {
        int r = row0 + (lane >> 2);
        int c = col0 + nt * 8 + (lane & 3) * 2;
        float bb0 = sm[B1_OFF + c], bb1 = sm[B1_OFF + c + 1];
        float v0 = f2tf(fmaxf(acc1[nt][0] + bb0, 0.f));
        float v1 = f2tf(fmaxf(acc1[nt][1] + bb1, 0.f));
        float v2 = f2tf(fmaxf(acc1[nt][2] + bb0, 0.f));
        float v3 = f2tf(fmaxf(acc1[nt][3] + bb1, 0.f));
        *(float2*)&sm[H1_OFF + r * LDH + c] = make_float2(v0, v1);
        *(float2*)&sm[H1_OFF + (r + 8) * LDH + c] = make_float2(v2, v3);
    }
    __syncthreads();

    // ================= GEMM2: [H2|G|TH|PH] = H1 @ W2ext + b2ext,  M128 N176 K128 ======
    float acc2[11][4];
#pragma unroll
    for (int nt = 0; nt < 11; nt++)
#pragma unroll
        for (int q = 0; q < 4; q++) acc2[nt][q] = 0.f;

    float4 pc[2];
    auto ldgB2 = [&](int kc) {
        int kb = kc * 16;
#pragma unroll
        for (int i = 0; i < 2; i++) {
            int f = tid + i * NTHREADS;
            if (f < 704) {
                int r = f / 44, c4 = f % 44;
                pc[i] = *(const float4*)(g_w2ext + (kb + r) * 176 + c4 * 4);
            }
        }
    };
    auto stsB2 = [&](int buf) {
#pragma unroll
        for (int i = 0; i < 2; i++) {
            int f = tid + i * NTHREADS;
            if (f < 704) {
                int r = f / 44, c4 = f % 44;
                float4 v = pc[i];
                v.x = f2tf(v.x); v.y = f2tf(v.y); v.z = f2tf(v.z); v.w = f2tf(v.w);
                *(float4*)&sm[BS2_OFF + buf * (16 * LDB2) + r * LDB2 + c4 * 4] = v;
            }
        }
    };

    ldgB2(0); stsB2(0);
    __syncthreads();

    for (int kc = 0; kc < 8; kc++) {
        int cur = kc & 1;
        if (kc + 1 < 8) ldgB2(kc + 1);
        const float* Bb = &sm[BS2_OFF + cur * (16 * LDB2)];
#pragma unroll
        for (int ks = 0; ks < 2; ks++) {
            int kg = kc * 16 + ks * 8;
            unsigned a[4];
            {
                int r = row0 + (lane >> 2);
                int c = kg + (lane & 3);
                a[0] = __float_as_uint(sm[H1_OFF + r * LDH + c]);
                a[1] = __float_as_uint(sm[H1_OFF + (r + 8) * LDH + c]);
                a[2] = __float_as_uint(sm[H1_OFF + r * LDH + c + 4]);
                a[3] = __float_as_uint(sm[H1_OFF + (r + 8) * LDH + c + 4]);
            }
#pragma unroll
            for (int nt = 0; nt < 11; nt++) {
                int kk = ks * 8 + (lane & 3);
                int c = wn * 88 + nt * 8 + (lane >> 2);
                unsigned b[2] = { __float_as_uint(Bb[kk * LDB2 + c]),
                                  __float_as_uint(Bb[(kk + 4) * LDB2 + c]) };
                mma8(acc2[nt], a, b);
            }
        }
        if (kc + 1 < 8) stsB2((kc + 1) & 1);
        __syncthreads();
    }
    // all H1/Bs2 reads done (loop-final sync) -> safe to overlay S2
#pragma unroll
    for (int nt = 0; nt < 11; nt++) {
        int r = row0 + (lane >> 2);
        int c = wn * 88 + nt * 8 + (lane & 3) * 2;
        float bb0 = sm[B2E_OFF + c], bb1 = sm[B2E_OFF + c + 1];
        *(float2*)&sm[S2_OFF + r * LDS2 + c] =
            make_float2(acc2[nt][0] + bb0, acc2[nt][1] + bb1);
        *(float2*)&sm[S2_OFF + (r + 8) * LDS2 + c] =
            make_float2(acc2[nt][2] + bb0, acc2[nt][3] + bb1);
    }
    __syncthreads();

    // ================= attention: Y[r][i] = softmax_j(ph_i*th_j) . g =================
    {
        int r = tid >> 2;
        int i0 = (tid & 3) * 4;
        const float* srow = &sm[S2_OFF + r * LDS2];
        float gg[16], th[16];
#pragma unroll
        for (int j = 0; j < 16; j++) { gg[j] = srow[128 + j]; th[j] = srow[144 + j]; }
#pragma unroll
        for (int i = i0; i < i0 + 4; i++) {
            float ph = srow[160 + i];
            float m = ph * th[0];
#pragma unroll
            for (int j = 1; j < 16; j++) m = fmaxf(m, ph * th[j]);
            float s = 0.f, ys = 0.f;
#pragma unroll
            for (int j = 0; j < 16; j++) {
                float e = __expf(ph * th[j] - m);
                s += e; ys += e * gg[j];
            }
            sm[YS_OFF + r * LDY + i] = f2tf(ys / s);
        }
    }
    __syncthreads();

    // ================= GEMM3: OUT = Y @ wo + bo + H2,  M128 N128 K16 =================
    float acc3[8][4];
#pragma unroll
    for (int nt = 0; nt < 8; nt++)
#pragma unroll
        for (int q = 0; q < 4; q++) acc3[nt][q] = 0.f;

#pragma unroll
    for (int ks = 0; ks < 2; ks++) {
        unsigned a[4];
        {
            int r = row0 + (lane >> 2);
            int c = ks * 8 + (lane & 3);
            a[0] = __float_as_uint(sm[YS_OFF + r * LDY + c]);
            a[1] = __float_as_uint(sm[YS_OFF + (r + 8) * LDY + c]);
            a[2] = __float_as_uint(sm[YS_OFF + r * LDY + c + 4]);
            a[3] = __float_as_uint(sm[YS_OFF + (r + 8) * LDY + c + 4]);
        }
#pragma unroll
        for (int nt = 0; nt < 8; nt++) {
            int kk = ks * 8 + (lane & 3);
            int c = col0 + nt * 8 + (lane >> 2);
            unsigned b[2] = { __float_as_uint(sm[WOS_OFF + kk * LDWO + c]),
                              __float_as_uint(sm[WOS_OFF + (kk + 4) * LDWO + c]) };
            mma8(acc3[nt], a, b);
        }
    }

#pragma unroll
    for (int nt = 0; nt < 8; nt++) {
        int r = row0 + (lane >> 2);
        int c = col0 + nt * 8 + (lane & 3) * 2;
        float bb0 = sm[BO_OFF + c], bb1 = sm[BO_OFF + c + 1];
        long e = e0 + r;
        if (e < E_TOTAL) {
            float o0 = acc3[nt][0] + sm[S2_OFF + r * LDS2 + c] + bb0;
            float o1 = acc3[nt][1] + sm[S2_OFF + r * LDS2 + c + 1] + bb1;
            *(float2*)&out[e * 128 + c] = make_float2(o0, o1);
        }
        long e2 = e + 8;
        if (e2 < E_TOTAL) {
            float o2 = acc3[nt][2] + sm[S2_OFF + (r + 8) * LDS2 + c] + bb0;
            float o3 = acc3[nt][3] + sm[S2_OFF + (r + 8) * LDS2 + c + 1] + bb1;
            *(float2*)&out[e2 * 128 + c] = make_float2(o2, o3);
        }
    }
}

extern "C" void kernel_launch(void* const* d_in, const int* in_sizes, int n_in,
                              void* d_out, int out_size) {
    const float* src = (const float*)d_in[0];
    const float* tgt = (const float*)d_in[1];
    const float* ea  = (const float*)d_in[2];
    const float* w1  = (const float*)d_in[3];
    const float* b1  = (const float*)d_in[4];
    const float* w2  = (const float*)d_in[5];
    const float* b2  = (const float*)d_in[6];
    const float* wg  = (const float*)d_in[7];
    const float* bg  = (const float*)d_in[8];
    const float* wt  = (const float*)d_in[9];
    const float* bt  = (const float*)d_in[10];
    const float* wp  = (const float*)d_in[11];
    const float* bp  = (const float*)d_in[12];
    const float* wo  = (const float*)d_in[13];
    const float* bo  = (const float*)d_in[14];
    float* out = (float*)d_out;

    cudaFuncSetAttribute(edge_att_kernel,
                         cudaFuncAttributeMaxDynamicSharedMemorySize, SMEM_BYTES);

    prep_kernel<<<176, 128>>>(w2, b2, wg, bg, wt, bt, wp, bp);

    int grid = (E_TOTAL + TILE_M - 1) / TILE_M;  // 2344
    edge_att_kernel<<<grid, NTHREADS, SMEM_BYTES>>>(src, tgt, ea, w1, b1, wo, bo, out);
}

// round 4
// speedup vs baseline: 1.3736x; 1.3524x over previous
#include <cuda_runtime.h>
#include <cstdint>

#define E_TOTAL 300000
#define NTH     512

// ---------------- shared memory layout (float offsets) ----------------
#define A1_OFF   0          // 3 stages x 4608 (128 x 36)
#define LDA1     36
#define A1_STAGE 4608
#define B1_OFF   13824      // 4 stages x 4096 (fragment-order chunk)
#define B1_STAGE 4096
#define B2_OFF   13824      // 2 stages x 6144 (overlay B1; phase-disjoint)
#define B2_STAGE 6144
#define GS_OFF   0          // 128 x 50 (g|th|ph)  (overlay A1 region)
#define LDGS     50
#define YS_OFF   6400       // 128 x 20
#define LDY      20
#define H1_OFF   30208      // 128 x 132
#define LDH      132
#define S2_OFF   30208      // overlay H1 (after GEMM2)
#define LDS2     132
#define WOS_OFF  47104      // 16 x 136
#define LDWO     136
#define B1B_OFF  49280      // 128
#define B2E_OFF  49408      // 192
#define BO_OFF   49600      // 128
#define SMEM_FLOATS 49728
#define SMEM_BYTES (SMEM_FLOATS * 4)

// ---------------- device-global prepped weights ----------------
// GEMM1 B: fragment-order, pre-rounded tf32: [kc(12)][ks(4)][wn(2)][p(4)][lane(32)][4]
__device__ float g_w1f[12 * 4096];
// w2ext transposed [n(192)][k(128)], n>=176 zero-padded
__device__ float g_w2e[192 * 128];
__device__ float g_b2e[192];
// GEMM2 B: fragment-order tf32: [kc(4)][ks(4)][wn(2)][p(6)][lane(32)][4]
__device__ float g_w2f[4 * 6144];

// ---------------- helpers ----------------
__device__ __forceinline__ float f2tf(float x) {
    unsigned u;
    asm("cvt.rna.tf32.f32 %0, %1;" : "=r"(u) : "f"(x));
    return __uint_as_float(u);
}
__device__ __forceinline__ uint32_t smem_u32(const void* p) {
    uint32_t a;
    asm("{ .reg .u64 t; cvta.to.shared.u64 t, %1; cvt.u32.u64 %0, t; }" : "=r"(a) : "l"(p));
    return a;
}
__device__ __forceinline__ void cp16(uint32_t s, const void* g) {
    asm volatile("cp.async.cg.shared.global [%0], [%1], 16;" :: "r"(s), "l"(g));
}
#define CP_COMMIT() asm volatile("cp.async.commit_group;" ::: "memory")
#define CP_WAIT(n)  asm volatile("cp.async.wait_group %0;" :: "n"(n) : "memory")

__device__ __forceinline__ void mma8(float* c, const unsigned* a, unsigned b0, unsigned b1) {
    asm volatile(
        "mma.sync.aligned.m16n8k8.row.col.f32.tf32.tf32.f32 "
        "{%0,%1,%2,%3}, {%4,%5,%6,%7}, {%8,%9}, {%0,%1,%2,%3};"
        : "+f"(c[0]), "+f"(c[1]), "+f"(c[2]), "+f"(c[3])
        : "r"(a[0]), "r"(a[1]), "r"(a[2]), "r"(a[3]), "r"(b0), "r"(b1));
}

// ---------------- prep kernels ----------------
// w2ext^T [n][k], zero pad n in [176,192)
__global__ void prep_w2e(const float* __restrict__ w2, const float* __restrict__ b2,
                         const float* __restrict__ wg, const float* __restrict__ bg,
                         const float* __restrict__ wt, const float* __restrict__ bt,
                         const float* __restrict__ wp, const float* __restrict__ bp) {
    int n = blockIdx.x;     // 0..191
    int k = threadIdx.x;    // 0..127
    float v = 0.f, b = 0.f;
    if (n < 128) {
        v = w2[k * 128 + n];
        b = b2[n];
    } else if (n < 176) {
        int p = (n - 128) >> 4, j = (n - 128) & 15;
        const float* W = (p == 0) ? wg : (p == 1) ? wt : wp;
        const float* B = (p == 0) ? bg : (p == 1) ? bt : bp;
        float s = 0.f;
        for (int m = 0; m < 128; m++) s += w2[k * 128 + m] * W[m * 16 + j];
        v = s;
        float sb = B[j];
        for (int m = 0; m < 128; m++) sb += b2[m] * W[m * 16 + j];
        b = sb;
    }
    g_w2e[n * 128 + k] = v;
    if (k == 0) g_b2e[n] = b;
}

// w1 -> fragment-order tf32
__global__ void prep_w1f(const float* __restrict__ w1) {
    int u = blockIdx.x * 128 + threadIdx.x;   // 0..12287 (16B units)
    int lane = u & 31;
    int p  = (u >> 5) & 3;
    int wn = (u >> 7) & 1;
    int ks = (u >> 8) & 3;
    int kc = u >> 10;
    int kk = lane & 3, cb = lane >> 2;
    int k0 = kc * 32 + ks * 8 + kk;
    int c  = wn * 64 + p * 16 + cb;
    float* o = g_w1f + u * 4;
    o[0] = f2tf(w1[k0 * 128 + c]);
    o[1] = f2tf(w1[(k0 + 4) * 128 + c]);
    o[2] = f2tf(w1[k0 * 128 + c + 8]);
    o[3] = f2tf(w1[(k0 + 4) * 128 + c + 8]);
}

// w2ext -> fragment-order tf32
__global__ void prep_w2f() {
    int u = blockIdx.x * 128 + threadIdx.x;   // 0..6143
    int lane = u & 31;
    int r = u >> 5;
    int p = r % 6; r /= 6;
    int wn = r & 1;
    int ks = (r >> 1) & 3;
    int kc = r >> 3;
    int kk = lane & 3, cb = lane >> 2;
    int k0 = kc * 32 + ks * 8 + kk;
    int c  = wn * 96 + p * 16 + cb;
    float* o = g_w2f + u * 4;
    o[0] = f2tf(g_w2e[c * 128 + k0]);
    o[1] = f2tf(g_w2e[c * 128 + k0 + 4]);
    o[2] = f2tf(g_w2e[(c + 8) * 128 + k0]);
    o[3] = f2tf(g_w2e[(c + 8) * 128 + k0 + 4]);
}

// ---------------- main fused kernel ----------------
extern __shared__ float sm[];

__global__ void __launch_bounds__(NTH, 1)
edge_att_kernel(const float* __restrict__ src, const float* __restrict__ tgt,
                const float* __restrict__ ea,
                const float* __restrict__ b1v, const float* __restrict__ wo,
                const float* __restrict__ bo,
                float* __restrict__ out) {
    const int tid  = threadIdx.x;
    const int lane = tid & 31;
    const int wid  = tid >> 5;       // 16 warps
    const int wm   = wid & 7;        // 8 M-warps (16 rows each)
    const int wn   = wid >> 3;       // 2 N-warps
    const int row0 = wm * 16;
    const long e0  = (long)blockIdx.x * 128;
    const uint32_t sbase = smem_u32(sm);

    // persistent small tiles
    for (int idx = tid; idx < 2048; idx += NTH) {
        int k = idx >> 7, n = idx & 127;
        sm[WOS_OFF + k * LDWO + n] = f2tf(wo[idx]);
    }
    if (tid < 128) sm[B1B_OFF + tid] = b1v[tid];
    if (tid < 128) sm[BO_OFF + tid] = bo[tid];
    if (tid < 192) sm[B2E_OFF + tid] = g_b2e[tid];

    // ---- staging lambdas ----
    auto ldgA = [&](int kc, float4* pr) {
        const float* sp = (kc < 4) ? src : (kc < 8) ? tgt : ea;
        int cin = (kc & 3) * 32;
#pragma unroll
        for (int i = 0; i < 2; i++) {
            int f = tid + i * NTH;
            int r = f >> 3, c4 = f & 7;
            long e = e0 + r; if (e >= E_TOTAL) e = E_TOTAL - 1;
            pr[i] = *(const float4*)(sp + e * 128 + cin + c4 * 4);
        }
    };
    auto stsA = [&](int kc, const float4* pr) {
        float* stage = &sm[A1_OFF + (kc % 3) * A1_STAGE];
#pragma unroll
        for (int i = 0; i < 2; i++) {
            int f = tid + i * NTH;
            int r = f >> 3, c4 = f & 7;
            float4 v = pr[i];
            v.x = f2tf(v.x); v.y = f2tf(v.y); v.z = f2tf(v.z); v.w = f2tf(v.w);
            *(float4*)&stage[r * LDA1 + c4 * 4] = v;
        }
    };
    auto cpB1 = [&](int kc) {
#pragma unroll
        for (int i = 0; i < 2; i++) {
            int f = tid + i * NTH;
            cp16(sbase + (B1_OFF + (kc & 3) * B1_STAGE + f * 4) * 4,
                 g_w1f + kc * 4096 + f * 4);
        }
    };
    auto cpB2 = [&](int kc) {
#pragma unroll
        for (int i = 0; i < 3; i++) {
            int f = tid + i * NTH;
            cp16(sbase + (B2_OFF + (kc & 1) * B2_STAGE + f * 4) * 4,
                 g_w2f + kc * 6144 + f * 4);
        }
    };

    // ================= GEMM1: H1 = relu(X @ w1 + b1), K=384, 12 chunks of 32 ==========
    float acc1[8][4];
#pragma unroll
    for (int nt = 0; nt < 8; nt++)
#pragma unroll
        for (int q = 0; q < 4; q++) acc1[nt][q] = 0.f;

    float4 pa[2][2];
    ldgA(0, pa[0]);
    stsA(0, pa[0]);
    ldgA(1, pa[1]);
    cpB1(0); CP_COMMIT();
    cpB1(1); CP_COMMIT();
    cpB1(2); CP_COMMIT();

#pragma unroll
    for (int kc = 0; kc < 12; kc++) {
        CP_WAIT(2);
        __syncthreads();
        if (kc + 2 < 12) ldgA(kc + 2, pa[kc & 1]);

        const float* Ab = &sm[A1_OFF + (kc % 3) * A1_STAGE];
        const uint4* Bb = (const uint4*)&sm[B1_OFF + (kc & 3) * B1_STAGE];
#pragma unroll
        for (int ks = 0; ks < 4; ks++) {
            unsigned a[4];
            int r = row0 + (lane >> 2);
            int ca = ks * 8 + (lane & 3);
            a[0] = __float_as_uint(Ab[r * LDA1 + ca]);
            a[1] = __float_as_uint(Ab[(r + 8) * LDA1 + ca]);
            a[2] = __float_as_uint(Ab[r * LDA1 + ca + 4]);
            a[3] = __float_as_uint(Ab[(r + 8) * LDA1 + ca + 4]);
#pragma unroll
            for (int p = 0; p < 4; p++) {
                uint4 bv = Bb[((ks * 2 + wn) * 4 + p) * 32 + lane];
                mma8(acc1[2 * p],     a, bv.x, bv.y);
                mma8(acc1[2 * p + 1], a, bv.z, bv.w);
            }
        }
        if (kc + 1 < 12) stsA(kc + 1, pa[(kc + 1) & 1]);
        if (kc + 3 < 12) cpB1(kc + 3);
        CP_COMMIT();
    }

    // ---- epilogue 1: H1 = tf32(relu(acc + b1)) ----
    {
        const int col0 = wn * 64;
#pragma unroll
        for (int nt = 0; nt < 8; nt++) {
            int r = row0 + (lane >> 2);
            int c = col0 + nt * 8 + (lane & 3) * 2;
            float bb0 = sm[B1B_OFF + c], bb1 = sm[B1B_OFF + c + 1];
            float v0 = f2tf(fmaxf(acc1[nt][0] + bb0, 0.f));
            float v1 = f2tf(fmaxf(acc1[nt][1] + bb1, 0.f));
            float v2 = f2tf(fmaxf(acc1[nt][2] + bb0, 0.f));
            float v3 = f2tf(fmaxf(acc1[nt][3] + bb1, 0.f));
            *(float2*)&sm[H1_OFF + r * LDH + c]       = make_float2(v0, v1);
            *(float2*)&sm[H1_OFF + (r + 8) * LDH + c] = make_float2(v2, v3);
        }
    }
    __syncthreads();   // H1 visible; all GEMM1 staging reads complete

    // ================= GEMM2: [H2|G|TH|PH|pad] = H1 @ w2ext, N=192, K=128 =============
    float acc2[12][4];
#pragma unroll
    for (int nt = 0; nt < 12; nt++)
#pragma unroll
        for (int q = 0; q < 4; q++) acc2[nt][q] = 0.f;

    cpB2(0); CP_COMMIT();
    cpB2(1); CP_COMMIT();

#pragma unroll
    for (int kc = 0; kc < 4; kc++) {
        CP_WAIT(1);
        __syncthreads();
        const uint4* Bb = (const uint4*)&sm[B2_OFF + (kc & 1) * B2_STAGE];
#pragma unroll
        for (int ks = 0; ks < 4; ks++) {
            unsigned a[4];
            int r = row0 + (lane >> 2);
            int ca = kc * 32 + ks * 8 + (lane & 3);
            a[0] = __float_as_uint(sm[H1_OFF + r * LDH + ca]);
            a[1] = __float_as_uint(sm[H1_OFF + (r + 8) * LDH + ca]);
            a[2] = __float_as_uint(sm[H1_OFF + r * LDH + ca + 4]);
            a[3] = __float_as_uint(sm[H1_OFF + (r + 8) * LDH + ca + 4]);
#pragma unroll
            for (int p = 0; p < 6; p++) {
                uint4 bv = Bb[((ks * 2 + wn) * 6 + p) * 32 + lane];
                mma8(acc2[2 * p],     a, bv.x, bv.y);
                mma8(acc2[2 * p + 1], a, bv.z, bv.w);
            }
        }
        __syncthreads();
        if (kc + 2 < 4) cpB2(kc + 2);
        CP_COMMIT();
    }

    // ---- epilogue 2: S2 (cols<128, overlays H1) ; GS (128..175) ----
#pragma unroll
    for (int nt = 0; nt < 12; nt++) {
        int r = row0 + (lane >> 2);
        int c = wn * 96 + nt * 8 + (lane & 3) * 2;
        if (c < 128) {
            float bb0 = sm[B2E_OFF + c], bb1 = sm[B2E_OFF + c + 1];
            *(float2*)&sm[S2_OFF + r * LDS2 + c] =
                make_float2(acc2[nt][0] + bb0, acc2[nt][1] + bb1);
            *(float2*)&sm[S2_OFF + (r + 8) * LDS2 + c] =
                make_float2(acc2[nt][2] + bb0, acc2[nt][3] + bb1);
        } else if (c < 176) {
            float bb0 = sm[B2E_OFF + c], bb1 = sm[B2E_OFF + c + 1];
            int cc = c - 128;
            *(float2*)&sm[GS_OFF + r * LDGS + cc] =
                make_float2(acc2[nt][0] + bb0, acc2[nt][1] + bb1);
            *(float2*)&sm[GS_OFF + (r + 8) * LDGS + cc] =
                make_float2(acc2[nt][2] + bb0, acc2[nt][3] + bb1);
        }
    }
    __syncthreads();

    // ================= attention softmax: Y[r][i] = softmax_j(ph_i*th_j) . g ==========
    {
        int r = tid >> 2;
        int i0 = (tid & 3) * 4;
        const float* srow = &sm[GS_OFF + r * LDGS];
        float gg[16], th[16];
#pragma unroll
        for (int j = 0; j < 16; j++) { gg[j] = srow[j]; th[j] = srow[16 + j]; }
#pragma unroll
        for (int i = i0; i < i0 + 4; i++) {
            float ph = srow[32 + i];
            float m = ph * th[0];
#pragma unroll
            for (int j = 1; j < 16; j++) m = fmaxf(m, ph * th[j]);
            float s = 0.f, ys = 0.f;
#pragma unroll
            for (int j = 0; j < 16; j++) {
                float e = __expf(ph * th[j] - m);
                s += e; ys += e * gg[j];
            }
            sm[YS_OFF + r * LDY + i] = f2tf(ys / s);
        }
    }
    __syncthreads();

    // ================= GEMM3: OUT = Y @ wo + bo + H2 (residual), K=16 =================
    {
        const int col0 = wn * 64;
        float acc3[8][4];
#pragma unroll
        for (int nt = 0; nt < 8; nt++)
#pragma unroll
            for (int q = 0; q < 4; q++) acc3[nt][q] = 0.f;

#pragma unroll
        for (int ks = 0; ks < 2; ks++) {
            unsigned a[4];
            int r = row0 + (lane >> 2);
            int ca = ks * 8 + (lane & 3);
            a[0] = __float_as_uint(sm[YS_OFF + r * LDY + ca]);
            a[1] = __float_as_uint(sm[YS_OFF + (r + 8) * LDY + ca]);
            a[2] = __float_as_uint(sm[YS_OFF + r * LDY + ca + 4]);
            a[3] = __float_as_uint(sm[YS_OFF + (r + 8) * LDY + ca + 4]);
#pragma unroll
            for (int nt = 0; nt < 8; nt++) {
                int kk = ks * 8 + (lane & 3);
                int c = col0 + nt * 8 + (lane >> 2);
                mma8(acc3[nt], a,
                     __float_as_uint(sm[WOS_OFF + kk * LDWO + c]),
                     __float_as_uint(sm[WOS_OFF + (kk + 4) * LDWO + c]));
            }
        }

#pragma unroll
        for (int nt = 0; nt < 8; nt++) {
            int r = row0 + (lane >> 2);
            int c = col0 + nt * 8 + (lane & 3) * 2;
            float bb0 = sm[BO_OFF + c], bb1 = sm[BO_OFF + c + 1];
            long e = e0 + r;
            if (e < E_TOTAL) {
                float o0 = acc3[nt][0] + sm[S2_OFF + r * LDS2 + c] + bb0;
                float o1 = acc3[nt][1] + sm[S2_OFF + r * LDS2 + c + 1] + bb1;
                *(float2*)&out[e * 128 + c] = make_float2(o0, o1);
            }
            long e2 = e + 8;
            if (e2 < E_TOTAL) {
                float o2 = acc3[nt][2] + sm[S2_OFF + (r + 8) * LDS2 + c] + bb0;
                float o3 = acc3[nt][3] + sm[S2_OFF + (r + 8) * LDS2 + c + 1] + bb1;
                *(float2*)&out[e2 * 128 + c] = make_float2(o2, o3);
            }
        }
    }
}

extern "C" void kernel_launch(void* const* d_in, const int* in_sizes, int n_in,
                              void* d_out, int out_size) {
    const float* src = (const float*)d_in[0];
    const float* tgt = (const float*)d_in[1];
    const float* ea  = (const float*)d_in[2];
    const float* w1  = (const float*)d_in[3];
    const float* b1  = (const float*)d_in[4];
    const float* w2  = (const float*)d_in[5];
    const float* b2  = (const float*)d_in[6];
    const float* wg  = (const float*)d_in[7];
    const float* bg  = (const float*)d_in[8];
    const float* wt  = (const float*)d_in[9];
    const float* bt  = (const float*)d_in[10];
    const float* wp  = (const float*)d_in[11];
    const float* bp  = (const float*)d_in[12];
    const float* wo  = (const float*)d_in[13];
    const float* bo  = (const float*)d_in[14];
    float* out = (float*)d_out;

    cudaFuncSetAttribute(edge_att_kernel,
                         cudaFuncAttributeMaxDynamicSharedMemorySize, SMEM_BYTES);

    prep_w2e<<<192, 128>>>(w2, b2, wg, bg, wt, bt, wp, bp);
    prep_w1f<<<96, 128>>>(w1);
    prep_w2f<<<48, 128>>>();

    int grid = (E_TOTAL + 127) / 128;   // 2344
    edge_att_kernel<<<grid, NTH, SMEM_BYTES>>>(src, tgt, ea, b1, wo, bo, out);
}

// round 5
// speedup vs baseline: 1.4598x; 1.0627x over previous
#include <cuda_runtime.h>
#include <cstdint>

#define E_TOTAL 300000
#define NTH     512

// ---------------- shared memory layout (float offsets) ----------------
#define A1_OFF   0          // 4 stages x 4608 (128 x 36), raw fp32
#define LDA1     36
#define A1_STAGE 4608
#define B1_OFF   18432      // 4 stages x 4096 (fragment-order)
#define B1_STAGE 4096
#define B2_OFF   18432      // 2 stages x 6144 (overlay B1; phase-disjoint)
#define B2_STAGE 6144
#define GS_OFF   0          // 128 x 50 (g|th|ph) overlay A1 ring
#define LDGS     50
#define YS_OFF   6400       // 128 x 20 (also within A1 region)
#define LDY      20
#define H1_OFF   34816      // 128 x 132
#define LDH      132
#define S2_OFF   34816      // overlay H1 (after GEMM2 reads done)
#define LDS2     132
#define WOS_OFF  51712      // 16 x 136
#define LDWO     136
#define B1B_OFF  53888      // 128
#define B2E_OFF  54016      // 192
#define BO_OFF   54208      // 128
#define SMEM_FLOATS 54336
#define SMEM_BYTES (SMEM_FLOATS * 4)   // 217,344 B

// ---------------- device-global prepped weights ----------------
// GEMM1 B frags: [kc(12)][ks(4)][wn(4)][p(2)][lane(32)][4]
__device__ __align__(16) float g_w1f[12 * 4096];
// w2ext^T [n(192)][k(128)], n>=176 zero
__device__ __align__(16) float g_w2e[192 * 128];
__device__ float g_b2e[192];
// GEMM2 B frags: [kc(4)][ks(4)][wn(4)][p(3)][lane(32)][4]
__device__ __align__(16) float g_w2f[4 * 6144];

// ---------------- helpers ----------------
__device__ __forceinline__ float f2tf(float x) {
    unsigned u;
    asm("cvt.rna.tf32.f32 %0, %1;" : "=r"(u) : "f"(x));
    return __uint_as_float(u);
}
__device__ __forceinline__ unsigned f2tfu(float x) {
    unsigned u;
    asm("cvt.rna.tf32.f32 %0, %1;" : "=r"(u) : "f"(x));
    return u;
}
__device__ __forceinline__ uint32_t smem_u32(const void* p) {
    uint32_t a;
    asm("{ .reg .u64 t; cvta.to.shared.u64 t, %1; cvt.u32.u64 %0, t; }" : "=r"(a) : "l"(p));
    return a;
}
__device__ __forceinline__ void cp16(uint32_t s, const void* g) {
    asm volatile("cp.async.cg.shared.global [%0], [%1], 16;" :: "r"(s), "l"(g));
}
#define CP_COMMIT() asm volatile("cp.async.commit_group;" ::: "memory")
#define CP_WAIT(n)  asm volatile("cp.async.wait_group %0;" :: "n"(n) : "memory")

__device__ __forceinline__ void mma8(float* c, const unsigned* a, unsigned b0, unsigned b1) {
    asm volatile(
        "mma.sync.aligned.m16n8k8.row.col.f32.tf32.tf32.f32 "
        "{%0,%1,%2,%3}, {%4,%5,%6,%7}, {%8,%9}, {%0,%1,%2,%3};"
        : "+f"(c[0]), "+f"(c[1]), "+f"(c[2]), "+f"(c[3])
        : "r"(a[0]), "r"(a[1]), "r"(a[2]), "r"(a[3]), "r"(b0), "r"(b1));
}

// ---------------- prep kernels ----------------
__global__ void prep_w2e(const float* __restrict__ w2, const float* __restrict__ b2,
                         const float* __restrict__ wg, const float* __restrict__ bg,
                         const float* __restrict__ wt, const float* __restrict__ bt,
                         const float* __restrict__ wp, const float* __restrict__ bp) {
    int n = blockIdx.x;     // 0..191
    int k = threadIdx.x;    // 0..127
    float v = 0.f, b = 0.f;
    if (n < 128) {
        v = w2[k * 128 + n];
        b = b2[n];
    } else if (n < 176) {
        int p = (n - 128) >> 4, j = (n - 128) & 15;
        const float* W = (p == 0) ? wg : (p == 1) ? wt : wp;
        const float* B = (p == 0) ? bg : (p == 1) ? bt : bp;
        float s = 0.f;
        for (int m = 0; m < 128; m++) s += w2[k * 128 + m] * W[m * 16 + j];
        v = s;
        float sb = B[j];
        for (int m = 0; m < 128; m++) sb += b2[m] * W[m * 16 + j];
        b = sb;
    }
    g_w2e[n * 128 + k] = v;
    if (k == 0) g_b2e[n] = b;
}

// w1 -> fragment order for 4M x 4N tiling
__global__ void prep_w1f(const float* __restrict__ w1) {
    int u = blockIdx.x * 128 + threadIdx.x;   // 0..12287
    int lane = u & 31;
    int r = u >> 5;
    int p  = r & 1;
    int wn = (r >> 1) & 3;
    int ks = (r >> 3) & 3;
    int kc = r >> 5;
    int kk = lane & 3, cb = lane >> 2;
    int k0 = kc * 32 + ks * 8 + kk;
    int c  = wn * 32 + p * 16 + cb;
    float* o = g_w1f + u * 4;
    o[0] = f2tf(w1[k0 * 128 + c]);
    o[1] = f2tf(w1[(k0 + 4) * 128 + c]);
    o[2] = f2tf(w1[k0 * 128 + c + 8]);
    o[3] = f2tf(w1[(k0 + 4) * 128 + c + 8]);
}

// w2ext -> fragment order for 4M x 4N (Nw=48) tiling
__global__ void prep_w2f() {
    int u = blockIdx.x * 128 + threadIdx.x;   // 0..6143
    int lane = u & 31;
    int r = u >> 5;                            // 0..191
    int p = r % 3; r /= 3;                     // 0..63
    int wn = r & 3;
    int ks = (r >> 2) & 3;
    int kc = r >> 4;
    int kk = lane & 3, cb = lane >> 2;
    int k0 = kc * 32 + ks * 8 + kk;
    int c  = wn * 48 + p * 16 + cb;
    float* o = g_w2f + u * 4;
    o[0] = f2tf(g_w2e[c * 128 + k0]);
    o[1] = f2tf(g_w2e[c * 128 + k0 + 4]);
    o[2] = f2tf(g_w2e[(c + 8) * 128 + k0]);
    o[3] = f2tf(g_w2e[(c + 8) * 128 + k0 + 4]);
}

// ---------------- main fused kernel ----------------
extern __shared__ float sm[];

__global__ void __launch_bounds__(NTH, 1)
edge_att_kernel(const float* __restrict__ src, const float* __restrict__ tgt,
                const float* __restrict__ ea,
                const float* __restrict__ b1v, const float* __restrict__ wo,
                const float* __restrict__ bo,
                float* __restrict__ out) {
    const int tid  = threadIdx.x;
    const int lane = tid & 31;
    const int wid  = tid >> 5;       // 16 warps: 4M x 4N
    const int wm   = wid & 3;
    const int wn   = wid >> 2;
    const int row0 = wm * 32;        // 32 rows / warp (2 m-tiles)
    const long e0  = (long)blockIdx.x * 128;
    const uint32_t sbase = smem_u32(sm);

    // persistent small tiles
    for (int idx = tid; idx < 2048; idx += NTH) {
        int k = idx >> 7, n = idx & 127;
        sm[WOS_OFF + k * LDWO + n] = f2tf(wo[idx]);
    }
    if (tid < 128) sm[B1B_OFF + tid] = b1v[tid];
    if (tid < 128) sm[BO_OFF + tid] = bo[tid];
    if (tid < 192) sm[B2E_OFF + tid] = g_b2e[tid];

    // ---- cp.async staging lambdas ----
    auto cpA = [&](int kc) {
        const float* sp = (kc < 4) ? src : (kc < 8) ? tgt : ea;
        int cin = (kc & 3) * 32;
        uint32_t sb = sbase + (A1_OFF + (kc & 3) * A1_STAGE) * 4;
#pragma unroll
        for (int i = 0; i < 2; i++) {
            int f = tid + i * NTH;
            int r = f >> 3, c4 = f & 7;
            long e = e0 + r; if (e >= E_TOTAL) e = E_TOTAL - 1;
            cp16(sb + (r * LDA1 + c4 * 4) * 4, sp + e * 128 + cin + c4 * 4);
        }
    };
    auto cpB1 = [&](int kc) {
        uint32_t sb = sbase + (B1_OFF + (kc & 3) * B1_STAGE) * 4;
#pragma unroll
        for (int i = 0; i < 2; i++) {
            int f = tid + i * NTH;
            cp16(sb + f * 16, g_w1f + kc * 4096 + f * 4);
        }
    };
    auto cpB2 = [&](int kc) {
        uint32_t sb = sbase + (B2_OFF + (kc & 1) * B2_STAGE) * 4;
#pragma unroll
        for (int i = 0; i < 3; i++) {
            int f = tid + i * NTH;
            cp16(sb + f * 16, g_w2f + kc * 6144 + f * 4);
        }
    };

    // ================= GEMM1: H1 = relu(X @ w1 + b1), K=384 (12 chunks of 32) =========
    float acc1[2][4][4];
#pragma unroll
    for (int mt = 0; mt < 2; mt++)
#pragma unroll
        for (int nt = 0; nt < 4; nt++)
#pragma unroll
            for (int q = 0; q < 4; q++) acc1[mt][nt][q] = 0.f;

    cpA(0); cpB1(0); CP_COMMIT();
    cpA(1); cpB1(1); CP_COMMIT();
    cpA(2); cpB1(2); CP_COMMIT();

#pragma unroll
    for (int kc = 0; kc < 12; kc++) {
        CP_WAIT(2);
        __syncthreads();
        if (kc + 3 < 12) { cpA(kc + 3); cpB1(kc + 3); }
        CP_COMMIT();

        const float* Ab = &sm[A1_OFF + (kc & 3) * A1_STAGE];
        const uint4* Bb = (const uint4*)&sm[B1_OFF + (kc & 3) * B1_STAGE];
#pragma unroll
        for (int ks = 0; ks < 4; ks++) {
            int r = row0 + (lane >> 2);
            int ca = ks * 8 + (lane & 3);
            unsigned a0[4], a1[4];
            a0[0] = f2tfu(Ab[r * LDA1 + ca]);
            a0[1] = f2tfu(Ab[(r + 8) * LDA1 + ca]);
            a0[2] = f2tfu(Ab[r * LDA1 + ca + 4]);
            a0[3] = f2tfu(Ab[(r + 8) * LDA1 + ca + 4]);
            a1[0] = f2tfu(Ab[(r + 16) * LDA1 + ca]);
            a1[1] = f2tfu(Ab[(r + 24) * LDA1 + ca]);
            a1[2] = f2tfu(Ab[(r + 16) * LDA1 + ca + 4]);
            a1[3] = f2tfu(Ab[(r + 24) * LDA1 + ca + 4]);
#pragma unroll
            for (int p = 0; p < 2; p++) {
                uint4 bv = Bb[((ks * 4 + wn) * 2 + p) * 32 + lane];
                mma8(acc1[0][2 * p],     a0, bv.x, bv.y);
                mma8(acc1[0][2 * p + 1], a0, bv.z, bv.w);
                mma8(acc1[1][2 * p],     a1, bv.x, bv.y);
                mma8(acc1[1][2 * p + 1], a1, bv.z, bv.w);
            }
        }
    }

    // ---- epilogue 1: H1 = tf32(relu(acc + b1)) ----
    {
        const int col0 = wn * 32;
#pragma unroll
        for (int mt = 0; mt < 2; mt++)
#pragma unroll
            for (int nt = 0; nt < 4; nt++) {
                int r = row0 + mt * 16 + (lane >> 2);
                int c = col0 + nt * 8 + (lane & 3) * 2;
                float bb0 = sm[B1B_OFF + c], bb1 = sm[B1B_OFF + c + 1];
                float v0 = f2tf(fmaxf(acc1[mt][nt][0] + bb0, 0.f));
                float v1 = f2tf(fmaxf(acc1[mt][nt][1] + bb1, 0.f));
                float v2 = f2tf(fmaxf(acc1[mt][nt][2] + bb0, 0.f));
                float v3 = f2tf(fmaxf(acc1[mt][nt][3] + bb1, 0.f));
                *(float2*)&sm[H1_OFF + r * LDH + c]       = make_float2(v0, v1);
                *(float2*)&sm[H1_OFF + (r + 8) * LDH + c] = make_float2(v2, v3);
            }
    }
    __syncthreads();   // H1 visible; GEMM1 staging regions free

    // ================= GEMM2: [H2|G|TH|PH|pad] = H1 @ w2ext, N=192, K=128 =============
    float acc2[2][6][4];
#pragma unroll
    for (int mt = 0; mt < 2; mt++)
#pragma unroll
        for (int nt = 0; nt < 6; nt++)
#pragma unroll
            for (int q = 0; q < 4; q++) acc2[mt][nt][q] = 0.f;

    cpB2(0); CP_COMMIT();
    cpB2(1); CP_COMMIT();

#pragma unroll
    for (int kc = 0; kc < 4; kc++) {
        CP_WAIT(1);
        __syncthreads();
        const uint4* Bb = (const uint4*)&sm[B2_OFF + (kc & 1) * B2_STAGE];
#pragma unroll
        for (int ks = 0; ks < 4; ks++) {
            int r = row0 + (lane >> 2);
            int ca = kc * 32 + ks * 8 + (lane & 3);
            unsigned a0[4], a1[4];
            a0[0] = __float_as_uint(sm[H1_OFF + r * LDH + ca]);
            a0[1] = __float_as_uint(sm[H1_OFF + (r + 8) * LDH + ca]);
            a0[2] = __float_as_uint(sm[H1_OFF + r * LDH + ca + 4]);
            a0[3] = __float_as_uint(sm[H1_OFF + (r + 8) * LDH + ca + 4]);
            a1[0] = __float_as_uint(sm[H1_OFF + (r + 16) * LDH + ca]);
            a1[1] = __float_as_uint(sm[H1_OFF + (r + 24) * LDH + ca]);
            a1[2] = __float_as_uint(sm[H1_OFF + (r + 16) * LDH + ca + 4]);
            a1[3] = __float_as_uint(sm[H1_OFF + (r + 24) * LDH + ca + 4]);
#pragma unroll
            for (int p = 0; p < 3; p++) {
                uint4 bv = Bb[((ks * 4 + wn) * 3 + p) * 32 + lane];
                mma8(acc2[0][2 * p],     a0, bv.x, bv.y);
                mma8(acc2[0][2 * p + 1], a0, bv.z, bv.w);
                mma8(acc2[1][2 * p],     a1, bv.x, bv.y);
                mma8(acc2[1][2 * p + 1], a1, bv.z, bv.w);
            }
        }
        __syncthreads();
        if (kc + 2 < 4) cpB2(kc + 2);
        CP_COMMIT();
    }

    // ---- epilogue 2: S2 (cols<128, overlays H1); GS (128..175) ----
#pragma unroll
    for (int mt = 0; mt < 2; mt++)
#pragma unroll
        for (int nt = 0; nt < 6; nt++) {
            int r = row0 + mt * 16 + (lane >> 2);
            int c = wn * 48 + nt * 8 + (lane & 3) * 2;
            float bb0 = sm[B2E_OFF + c], bb1 = sm[B2E_OFF + c + 1];
            float v0 = acc2[mt][nt][0] + bb0, v1 = acc2[mt][nt][1] + bb1;
            float v2 = acc2[mt][nt][2] + bb0, v3 = acc2[mt][nt][3] + bb1;
            if (c < 128) {
                *(float2*)&sm[S2_OFF + r * LDS2 + c]       = make_float2(v0, v1);
                *(float2*)&sm[S2_OFF + (r + 8) * LDS2 + c] = make_float2(v2, v3);
            } else if (c < 176) {
                int cc = c - 128;
                *(float2*)&sm[GS_OFF + r * LDGS + cc]       = make_float2(v0, v1);
                *(float2*)&sm[GS_OFF + (r + 8) * LDGS + cc] = make_float2(v2, v3);
            }
        }
    __syncthreads();

    // ================= attention softmax: Y[r][i] = softmax_j(ph_i*th_j) . g ==========
    {
        int r = tid >> 2;
        int i0 = (tid & 3) * 4;
        const float* srow = &sm[GS_OFF + r * LDGS];
        float gg[16], th[16];
#pragma unroll
        for (int j = 0; j < 16; j++) { gg[j] = srow[j]; th[j] = srow[16 + j]; }
#pragma unroll
        for (int i = i0; i < i0 + 4; i++) {
            float ph = srow[32 + i];
            float m = ph * th[0];
#pragma unroll
            for (int j = 1; j < 16; j++) m = fmaxf(m, ph * th[j]);
            float s = 0.f, ys = 0.f;
#pragma unroll
            for (int j = 0; j < 16; j++) {
                float e = __expf(ph * th[j] - m);
                s += e; ys += e * gg[j];
            }
            sm[YS_OFF + r * LDY + i] = f2tf(ys / s);
        }
    }
    __syncthreads();

    // ================= GEMM3: OUT = Y @ wo + bo + H2 (residual), K=16 =================
    {
        const int row0g = (wid & 7) * 16;
        const int col0g = (wid >> 3) * 64;
        float acc3[8][4];
#pragma unroll
        for (int nt = 0; nt < 8; nt++)
#pragma unroll
            for (int q = 0; q < 4; q++) acc3[nt][q] = 0.f;

#pragma unroll
        for (int ks = 0; ks < 2; ks++) {
            unsigned a[4];
            int r = row0g + (lane >> 2);
            int ca = ks * 8 + (lane & 3);
            a[0] = __float_as_uint(sm[YS_OFF + r * LDY + ca]);
            a[1] = __float_as_uint(sm[YS_OFF + (r + 8) * LDY + ca]);
            a[2] = __float_as_uint(sm[YS_OFF + r * LDY + ca + 4]);
            a[3] = __float_as_uint(sm[YS_OFF + (r + 8) * LDY + ca + 4]);
#pragma unroll
            for (int nt = 0; nt < 8; nt++) {
                int kk = ks * 8 + (lane & 3);
                int c = col0g + nt * 8 + (lane >> 2);
                mma8(acc3[nt], a,
                     __float_as_uint(sm[WOS_OFF + kk * LDWO + c]),
                     __float_as_uint(sm[WOS_OFF + (kk + 4) * LDWO + c]));
            }
        }

#pragma unroll
        for (int nt = 0; nt < 8; nt++) {
            int r = row0g + (lane >> 2);
            int c = col0g + nt * 8 + (lane & 3) * 2;
            float bb0 = sm[BO_OFF + c], bb1 = sm[BO_OFF + c + 1];
            long e = e0 + r;
            if (e < E_TOTAL) {
                float o0 = acc3[nt][0] + sm[S2_OFF + r * LDS2 + c] + bb0;
                float o1 = acc3[nt][1] + sm[S2_OFF + r * LDS2 + c + 1] + bb1;
                *(float2*)&out[e * 128 + c] = make_float2(o0, o1);
            }
            long e2 = e + 8;
            if (e2 < E_TOTAL) {
                float o2 = acc3[nt][2] + sm[S2_OFF + (r + 8) * LDS2 + c] + bb0;
                float o3 = acc3[nt][3] + sm[S2_OFF + (r + 8) * LDS2 + c + 1] + bb1;
                *(float2*)&out[e2 * 128 + c] = make_float2(o2, o3);
            }
        }
    }
}

extern "C" void kernel_launch(void* const* d_in, const int* in_sizes, int n_in,
                              void* d_out, int out_size) {
    const float* src = (const float*)d_in[0];
    const float* tgt = (const float*)d_in[1];
    const float* ea  = (const float*)d_in[2];
    const float* w1  = (const float*)d_in[3];
    const float* b1  = (const float*)d_in[4];
    const float* w2  = (const float*)d_in[5];
    const float* b2  = (const float*)d_in[6];
    const float* wg  = (const float*)d_in[7];
    const float* bg  = (const float*)d_in[8];
    const float* wt  = (const float*)d_in[9];
    const float* bt  = (const float*)d_in[10];
    const float* wp  = (const float*)d_in[11];
    const float* bp  = (const float*)d_in[12];
    const float* wo  = (const float*)d_in[13];
    const float* bo  = (const float*)d_in[14];
    float* out = (float*)d_out;

    cudaFuncSetAttribute(edge_att_kernel,
                         cudaFuncAttributeMaxDynamicSharedMemorySize, SMEM_BYTES);

    prep_w2e<<<192, 128>>>(w2, b2, wg, bg, wt, bt, wp, bp);
    prep_w1f<<<96, 128>>>(w1);
    prep_w2f<<<48, 128>>>();

    int grid = (E_TOTAL + 127) / 128;   // 2344
    edge_att_kernel<<<grid, NTH, SMEM_BYTES>>>(src, tgt, ea, b1, wo, bo, out);
}

// round 6
// speedup vs baseline: 1.6824x; 1.1525x over previous
#include <cuda_runtime.h>
#include <cstdint>

#define E_TOTAL 300000
#define TILE_M  64
#define NTH     256

// ---------------- shared memory layout (float offsets) ----------------
#define A1_OFF   0          // 3 stages x 2304 (64 x 36), raw fp32
#define LDA1     36
#define A1_STAGE 2304
#define B1_OFF   6912       // 3 stages x 4096 (fragment-order, k32 chunks)
#define B1_STAGE 4096
#define B2_OFF   6912       // 4 stages x 3072 (k16 chunks; overlay B1, phase-disjoint)
#define B2_STAGE 3072
#define H1_OFF   19200      // 64 x 132
#define LDH      132
#define S2_OFF   19200      // overlay H1 (after GEMM2 reads done)
#define LDS2     132
#define GS_OFF   0          // 64 x 50 (g|th|ph), overlay A1 ring
#define LDGS     50
#define YS_OFF   3200       // 64 x 20
#define LDY      20
#define WOF_OFF  4480       // 2048 fl wo fragments (within A1 region)
#define B1B_OFF  27648      // 128
#define B2E_OFF  27776      // 192
#define BO_OFF   27968      // 128
#define SMEM_FLOATS 28096
#define SMEM_BYTES (SMEM_FLOATS * 4)   // 112,384 B -> 2 CTAs/SM

// ---------------- device-global prepped weights ----------------
// GEMM1 B frags: [kc(12)][ks(4)][wn(4)][p(2)][lane(32)][4]
__device__ __align__(16) float g_w1f[12 * 4096];
// w2ext^T [n(192)][k(128)], n>=176 zero
__device__ __align__(16) float g_w2e[192 * 128];
__device__ float g_b2e[192];
// GEMM2 B frags (k16 chunks): [kc(8)][ks(2)][wn(4)][p(3)][lane(32)][4]
__device__ __align__(16) float g_w2f[8 * 3072];
// GEMM3 wo frags: [ks(2)][wn(2)][p(4)][lane(32)][4]
__device__ __align__(16) float g_wof[2048];

// ---------------- helpers ----------------
__device__ __forceinline__ float f2tf(float x) {
    unsigned u;
    asm("cvt.rna.tf32.f32 %0, %1;" : "=r"(u) : "f"(x));
    return __uint_as_float(u);
}
__device__ __forceinline__ unsigned f2tfu(float x) {
    unsigned u;
    asm("cvt.rna.tf32.f32 %0, %1;" : "=r"(u) : "f"(x));
    return u;
}
__device__ __forceinline__ uint32_t smem_u32(const void* p) {
    uint32_t a;
    asm("{ .reg .u64 t; cvta.to.shared.u64 t, %1; cvt.u32.u64 %0, t; }" : "=r"(a) : "l"(p));
    return a;
}
__device__ __forceinline__ void cp16(uint32_t s, const void* g) {
    asm volatile("cp.async.cg.shared.global [%0], [%1], 16;" :: "r"(s), "l"(g));
}
#define CP_COMMIT() asm volatile("cp.async.commit_group;" ::: "memory")
#define CP_WAIT(n)  asm volatile("cp.async.wait_group %0;" :: "n"(n) : "memory")

__device__ __forceinline__ void mma8(float* c, const unsigned* a, unsigned b0, unsigned b1) {
    asm volatile(
        "mma.sync.aligned.m16n8k8.row.col.f32.tf32.tf32.f32 "
        "{%0,%1,%2,%3}, {%4,%5,%6,%7}, {%8,%9}, {%0,%1,%2,%3};"
        : "+f"(c[0]), "+f"(c[1]), "+f"(c[2]), "+f"(c[3])
        : "r"(a[0]), "r"(a[1]), "r"(a[2]), "r"(a[3]), "r"(b0), "r"(b1));
}

// ---------------- prep kernels ----------------
__global__ void prep_w2e(const float* __restrict__ w2, const float* __restrict__ b2,
                         const float* __restrict__ wg, const float* __restrict__ bg,
                         const float* __restrict__ wt, const float* __restrict__ bt,
                         const float* __restrict__ wp, const float* __restrict__ bp) {
    int n = blockIdx.x;     // 0..191
    int k = threadIdx.x;    // 0..127
    float v = 0.f, b = 0.f;
    if (n < 128) {
        v = w2[k * 128 + n];
        b = b2[n];
    } else if (n < 176) {
        int p = (n - 128) >> 4, j = (n - 128) & 15;
        const float* W = (p == 0) ? wg : (p == 1) ? wt : wp;
        const float* B = (p == 0) ? bg : (p == 1) ? bt : bp;
        float s = 0.f;
        for (int m = 0; m < 128; m++) s += w2[k * 128 + m] * W[m * 16 + j];
        v = s;
        float sb = B[j];
        for (int m = 0; m < 128; m++) sb += b2[m] * W[m * 16 + j];
        b = sb;
    }
    g_w2e[n * 128 + k] = v;
    if (k == 0) g_b2e[n] = b;
}

// w1 -> fragment order: [kc(12)][ks(4)][wn(4)][p(2)][lane][4]
__global__ void prep_w1f(const float* __restrict__ w1) {
    int u = blockIdx.x * 128 + threadIdx.x;   // 0..12287 (uint4 units)
    int lane = u & 31;
    int r = u >> 5;
    int p  = r & 1;
    int wn = (r >> 1) & 3;
    int ks = (r >> 3) & 3;
    int kc = r >> 5;
    int kk = lane & 3, cb = lane >> 2;
    int k0 = kc * 32 + ks * 8 + kk;
    int c  = wn * 32 + p * 16 + cb;
    float* o = g_w1f + u * 4;
    o[0] = f2tf(w1[k0 * 128 + c]);
    o[1] = f2tf(w1[(k0 + 4) * 128 + c]);
    o[2] = f2tf(w1[k0 * 128 + c + 8]);
    o[3] = f2tf(w1[(k0 + 4) * 128 + c + 8]);
}

// w2ext -> fragment order: [kc(8)][ks(2)][wn(4)][p(3)][lane][4]
__global__ void prep_w2f() {
    int u = blockIdx.x * 128 + threadIdx.x;   // 0..6143
    int lane = u & 31;
    int r = u >> 5;                            // 0..191
    int p = r % 3; r /= 3;                     // 0..63
    int wn = r & 3;
    int ks = (r >> 2) & 1;
    int kc = r >> 3;                           // 0..7
    int kk = lane & 3, cb = lane >> 2;
    int k0 = kc * 16 + ks * 8 + kk;
    int c  = wn * 48 + p * 16 + cb;
    float* o = g_w2f + u * 4;
    o[0] = f2tf(g_w2e[c * 128 + k0]);
    o[1] = f2tf(g_w2e[c * 128 + k0 + 4]);
    o[2] = f2tf(g_w2e[(c + 8) * 128 + k0]);
    o[3] = f2tf(g_w2e[(c + 8) * 128 + k0 + 4]);
}

// wo -> fragment order: [ks(2)][wn(2)][p(4)][lane][4]
__global__ void prep_wof(const float* __restrict__ wo) {
    int u = blockIdx.x * 128 + threadIdx.x;   // 0..511
    int lane = u & 31;
    int r = u >> 5;                            // 0..15
    int p  = r & 3;
    int wn = (r >> 2) & 1;
    int ks = r >> 3;
    int kk = lane & 3, cb = lane >> 2;
    int k0 = ks * 8 + kk;
    int c  = wn * 64 + p * 16 + cb;
    float* o = g_wof + u * 4;
    o[0] = f2tf(wo[k0 * 128 + c]);
    o[1] = f2tf(wo[(k0 + 4) * 128 + c]);
    o[2] = f2tf(wo[k0 * 128 + c + 8]);
    o[3] = f2tf(wo[(k0 + 4) * 128 + c + 8]);
}

// ---------------- main fused kernel: 64 edges/CTA, 256 threads, 2 CTA/SM ----------------
extern __shared__ float sm[];

__global__ void __launch_bounds__(NTH, 2)
edge_att_kernel(const float* __restrict__ src, const float* __restrict__ tgt,
                const float* __restrict__ ea,
                const float* __restrict__ b1v, const float* __restrict__ bo,
                float* __restrict__ out) {
    const int tid  = threadIdx.x;
    const int lane = tid & 31;
    const int wid  = tid >> 5;       // 8 warps
    const int wm   = wid & 1;        // 2 M-warps (32 rows each)
    const int wn   = wid >> 1;       // 4 N-warps
    const int row0 = wm * 32;
    const long e0  = (long)blockIdx.x * TILE_M;
    const uint32_t sbase = smem_u32(sm);

    // persistent biases
    if (tid < 128) sm[B1B_OFF + tid] = b1v[tid];
    if (tid < 128) sm[BO_OFF + tid] = bo[tid];
    if (tid < 192) sm[B2E_OFF + tid] = g_b2e[tid];

    // ---- cp.async staging lambdas ----
    auto cpA = [&](int kc) {
        const float* sp = (kc < 4) ? src : (kc < 8) ? tgt : ea;
        int cin = (kc & 3) * 32;
        uint32_t sb = sbase + (A1_OFF + (kc % 3) * A1_STAGE) * 4;
#pragma unroll
        for (int i = 0; i < 2; i++) {
            int f = tid + i * NTH;           // 0..511
            int r = f >> 3, c4 = f & 7;
            long e = e0 + r; if (e >= E_TOTAL) e = E_TOTAL - 1;
            cp16(sb + (r * LDA1 + c4 * 4) * 4, sp + e * 128 + cin + c4 * 4);
        }
    };
    auto cpB1 = [&](int kc) {
        uint32_t sb = sbase + (B1_OFF + (kc % 3) * B1_STAGE) * 4;
#pragma unroll
        for (int i = 0; i < 4; i++) {
            int f = tid + i * NTH;
            cp16(sb + f * 16, g_w1f + kc * 4096 + f * 4);
        }
    };
    auto cpB2 = [&](int kc) {
        uint32_t sb = sbase + (B2_OFF + (kc & 3) * B2_STAGE) * 4;
#pragma unroll
        for (int i = 0; i < 3; i++) {
            int f = tid + i * NTH;
            cp16(sb + f * 16, g_w2f + kc * 3072 + f * 4);
        }
    };
    auto cpWOF = [&]() {
        uint32_t sb = sbase + WOF_OFF * 4;
#pragma unroll
        for (int i = 0; i < 2; i++) {
            int f = tid + i * NTH;
            cp16(sb + f * 16, g_wof + f * 4);
        }
    };

    // ================= GEMM1: H1 = relu(X @ w1 + b1), K=384 (12 chunks of 32) =========
    float acc1[2][4][4];
#pragma unroll
    for (int mt = 0; mt < 2; mt++)
#pragma unroll
        for (int nt = 0; nt < 4; nt++)
#pragma unroll
            for (int q = 0; q < 4; q++) acc1[mt][nt][q] = 0.f;

    cpA(0); cpB1(0); CP_COMMIT();
    cpA(1); cpB1(1); CP_COMMIT();

#pragma unroll
    for (int kc = 0; kc < 12; kc++) {
        CP_WAIT(1);
        __syncthreads();
        if (kc + 2 < 12) { cpA(kc + 2); cpB1(kc + 2); }
        CP_COMMIT();

        const float* Ab = &sm[A1_OFF + (kc % 3) * A1_STAGE];
        const uint4* Bb = (const uint4*)&sm[B1_OFF + (kc % 3) * B1_STAGE];
#pragma unroll
        for (int ks = 0; ks < 4; ks++) {
            int r = row0 + (lane >> 2);
            int ca = ks * 8 + (lane & 3);
            unsigned a0[4], a1[4];
            a0[0] = f2tfu(Ab[r * LDA1 + ca]);
            a0[1] = f2tfu(Ab[(r + 8) * LDA1 + ca]);
            a0[2] = f2tfu(Ab[r * LDA1 + ca + 4]);
            a0[3] = f2tfu(Ab[(r + 8) * LDA1 + ca + 4]);
            a1[0] = f2tfu(Ab[(r + 16) * LDA1 + ca]);
            a1[1] = f2tfu(Ab[(r + 24) * LDA1 + ca]);
            a1[2] = f2tfu(Ab[(r + 16) * LDA1 + ca + 4]);
            a1[3] = f2tfu(Ab[(r + 24) * LDA1 + ca + 4]);
#pragma unroll
            for (int p = 0; p < 2; p++) {
                uint4 bv = Bb[((ks * 4 + wn) * 2 + p) * 32 + lane];
                mma8(acc1[0][2 * p],     a0, bv.x, bv.y);
                mma8(acc1[0][2 * p + 1], a0, bv.z, bv.w);
                mma8(acc1[1][2 * p],     a1, bv.x, bv.y);
                mma8(acc1[1][2 * p + 1], a1, bv.z, bv.w);
            }
        }
    }

    // ---- epilogue 1: H1 = tf32(relu(acc + b1)) ----
    {
        const int col0 = wn * 32;
#pragma unroll
        for (int mt = 0; mt < 2; mt++)
#pragma unroll
            for (int nt = 0; nt < 4; nt++) {
                int r = row0 + mt * 16 + (lane >> 2);
                int c = col0 + nt * 8 + (lane & 3) * 2;
                float bb0 = sm[B1B_OFF + c], bb1 = sm[B1B_OFF + c + 1];
                float v0 = f2tf(fmaxf(acc1[mt][nt][0] + bb0, 0.f));
                float v1 = f2tf(fmaxf(acc1[mt][nt][1] + bb1, 0.f));
                float v2 = f2tf(fmaxf(acc1[mt][nt][2] + bb0, 0.f));
                float v3 = f2tf(fmaxf(acc1[mt][nt][3] + bb1, 0.f));
                *(float2*)&sm[H1_OFF + r * LDH + c]       = make_float2(v0, v1);
                *(float2*)&sm[H1_OFF + (r + 8) * LDH + c] = make_float2(v2, v3);
            }
    }
    __syncthreads();   // H1 visible; A1/B1 rings retired

    // ================= GEMM2: [H2|G|TH|PH|pad] = H1 @ w2ext, N=192, K=128 (8 x k16) ===
    float acc2[2][6][4];
#pragma unroll
    for (int mt = 0; mt < 2; mt++)
#pragma unroll
        for (int nt = 0; nt < 6; nt++)
#pragma unroll
            for (int q = 0; q < 4; q++) acc2[mt][nt][q] = 0.f;

    cpWOF(); cpB2(0); CP_COMMIT();
    cpB2(1); CP_COMMIT();
    cpB2(2); CP_COMMIT();

#pragma unroll
    for (int kc = 0; kc < 8; kc++) {
        CP_WAIT(2);
        __syncthreads();
        if (kc + 3 < 8) cpB2(kc + 3);
        CP_COMMIT();

        const uint4* Bb = (const uint4*)&sm[B2_OFF + (kc & 3) * B2_STAGE];
#pragma unroll
        for (int ks = 0; ks < 2; ks++) {
            int r = row0 + (lane >> 2);
            int ca = kc * 16 + ks * 8 + (lane & 3);
            unsigned a0[4], a1[4];
            a0[0] = __float_as_uint(sm[H1_OFF + r * LDH + ca]);
            a0[1] = __float_as_uint(sm[H1_OFF + (r + 8) * LDH + ca]);
            a0[2] = __float_as_uint(sm[H1_OFF + r * LDH + ca + 4]);
            a0[3] = __float_as_uint(sm[H1_OFF + (r + 8) * LDH + ca + 4]);
            a1[0] = __float_as_uint(sm[H1_OFF + (r + 16) * LDH + ca]);
            a1[1] = __float_as_uint(sm[H1_OFF + (r + 24) * LDH + ca]);
            a1[2] = __float_as_uint(sm[H1_OFF + (r + 16) * LDH + ca + 4]);
            a1[3] = __float_as_uint(sm[H1_OFF + (r + 24) * LDH + ca + 4]);
#pragma unroll
            for (int p = 0; p < 3; p++) {
                uint4 bv = Bb[((ks * 4 + wn) * 3 + p) * 32 + lane];
                mma8(acc2[0][2 * p],     a0, bv.x, bv.y);
                mma8(acc2[0][2 * p + 1], a0, bv.z, bv.w);
                mma8(acc2[1][2 * p],     a1, bv.x, bv.y);
                mma8(acc2[1][2 * p + 1], a1, bv.z, bv.w);
            }
        }
    }
    __syncthreads();   // all H1 reads done -> safe to overlay S2

    // ---- epilogue 2: S2 (cols<128, overlays H1); GS (128..175) ----
#pragma unroll
    for (int mt = 0; mt < 2; mt++)
#pragma unroll
        for (int nt = 0; nt < 6; nt++) {
            int r = row0 + mt * 16 + (lane >> 2);
            int c = wn * 48 + nt * 8 + (lane & 3) * 2;
            float bb0 = sm[B2E_OFF + c], bb1 = sm[B2E_OFF + c + 1];
            float v0 = acc2[mt][nt][0] + bb0, v1 = acc2[mt][nt][1] + bb1;
            float v2 = acc2[mt][nt][2] + bb0, v3 = acc2[mt][nt][3] + bb1;
            if (c < 128) {
                *(float2*)&sm[S2_OFF + r * LDS2 + c]       = make_float2(v0, v1);
                *(float2*)&sm[S2_OFF + (r + 8) * LDS2 + c] = make_float2(v2, v3);
            } else if (c < 176) {
                int cc = c - 128;
                *(float2*)&sm[GS_OFF + r * LDGS + cc]       = make_float2(v0, v1);
                *(float2*)&sm[GS_OFF + (r + 8) * LDGS + cc] = make_float2(v2, v3);
            }
        }
    __syncthreads();

    // ================= attention softmax: Y[r][i] = softmax_j(ph_i*th_j) . g ==========
    {
        int r = tid >> 2;                  // 0..63
        int i0 = (tid & 3) * 4;
        const float* srow = &sm[GS_OFF + r * LDGS];
        float gg[16], th[16];
#pragma unroll
        for (int j = 0; j < 16; j++) { gg[j] = srow[j]; th[j] = srow[16 + j]; }
#pragma unroll
        for (int i = i0; i < i0 + 4; i++) {
            float ph = srow[32 + i];
            float m = ph * th[0];
#pragma unroll
            for (int j = 1; j < 16; j++) m = fmaxf(m, ph * th[j]);
            float s = 0.f, ys = 0.f;
#pragma unroll
            for (int j = 0; j < 16; j++) {
                float e = __expf(ph * th[j] - m);
                s += e; ys += e * gg[j];
            }
            sm[YS_OFF + r * LDY + i] = f2tf(ys / s);
        }
    }
    CP_WAIT(0);        // wo fragments resident
    __syncthreads();

    // ================= GEMM3: OUT = Y @ wo + bo + H2 (residual), K=16 =================
    {
        const int row0g = (wid & 3) * 16;
        const int col0g = (wid >> 2) * 64;
        const uint4* Wf = (const uint4*)&sm[WOF_OFF];
        float acc3[8][4];
#pragma unroll
        for (int nt = 0; nt < 8; nt++)
#pragma unroll
            for (int q = 0; q < 4; q++) acc3[nt][q] = 0.f;

#pragma unroll
        for (int ks = 0; ks < 2; ks++) {
            unsigned a[4];
            int r = row0g + (lane >> 2);
            int ca = ks * 8 + (lane & 3);
            a[0] = __float_as_uint(sm[YS_OFF + r * LDY + ca]);
            a[1] = __float_as_uint(sm[YS_OFF + (r + 8) * LDY + ca]);
            a[2] = __float_as_uint(sm[YS_OFF + r * LDY + ca + 4]);
            a[3] = __float_as_uint(sm[YS_OFF + (r + 8) * LDY + ca + 4]);
#pragma unroll
            for (int p = 0; p < 4; p++) {
                uint4 bv = Wf[((ks * 2 + (wid >> 2)) * 4 + p) * 32 + lane];
                mma8(acc3[2 * p],     a, bv.x, bv.y);
                mma8(acc3[2 * p + 1], a, bv.z, bv.w);
            }
        }

#pragma unroll
        for (int nt = 0; nt < 8; nt++) {
            int r = row0g + (lane >> 2);
            int c = col0g + nt * 8 + (lane & 3) * 2;
            float bb0 = sm[BO_OFF + c], bb1 = sm[BO_OFF + c + 1];
            long e = e0 + r;
            if (e < E_TOTAL) {
                float o0 = acc3[nt][0] + sm[S2_OFF + r * LDS2 + c] + bb0;
                float o1 = acc3[nt][1] + sm[S2_OFF + r * LDS2 + c + 1] + bb1;
                *(float2*)&out[e * 128 + c] = make_float2(o0, o1);
            }
            long e2 = e + 8;
            if (e2 < E_TOTAL) {
                float o2 = acc3[nt][2] + sm[S2_OFF + (r + 8) * LDS2 + c] + bb0;
                float o3 = acc3[nt][3] + sm[S2_OFF + (r + 8) * LDS2 + c + 1] + bb1;
                *(float2*)&out[e2 * 128 + c] = make_float2(o2, o3);
            }
        }
    }
}

extern "C" void kernel_launch(void* const* d_in, const int* in_sizes, int n_in,
                              void* d_out, int out_size) {
    const float* src = (const float*)d_in[0];
    const float* tgt = (const float*)d_in[1];
    const float* ea  = (const float*)d_in[2];
    const float* w1  = (const float*)d_in[3];
    const float* b1  = (const float*)d_in[4];
    const float* w2  = (const float*)d_in[5];
    const float* b2  = (const float*)d_in[6];
    const float* wg  = (const float*)d_in[7];
    const float* bg  = (const float*)d_in[8];
    const float* wt  = (const float*)d_in[9];
    const float* bt  = (const float*)d_in[10];
    const float* wp  = (const float*)d_in[11];
    const float* bp  = (const float*)d_in[12];
    const float* wo  = (const float*)d_in[13];
    const float* bo  = (const float*)d_in[14];
    float* out = (float*)d_out;

    cudaFuncSetAttribute(edge_att_kernel,
                         cudaFuncAttributeMaxDynamicSharedMemorySize, SMEM_BYTES);

    prep_w2e<<<192, 128>>>(w2, b2, wg, bg, wt, bt, wp, bp);
    prep_w1f<<<96, 128>>>(w1);
    prep_w2f<<<48, 128>>>();
    prep_wof<<<4, 128>>>(wo);

    int grid = (E_TOTAL + TILE_M - 1) / TILE_M;   // 4688
    edge_att_kernel<<<grid, NTH, SMEM_BYTES>>>(src, tgt, ea, b1, bo, out);
}

// round 7
// speedup vs baseline: 2.1528x; 1.2796x over previous
#include <cuda_runtime.h>
#include <cuda_fp16.h>
#include <cstdint>

#define E_TOTAL 300000
#define TILE_M  64
#define NTH     256

// ---------------- shared memory byte offsets ----------------
// Phase 1 (GEMM1): A1 ring (3x5120) + B1 ring (3x8192)
// Phase 2 (GEMM2): B2 ring (4x6144) + WOF, overlaying phase-1 rings
// Phase 3 (softmax/GEMM3): GS/Y overlay ring region
#define A1B(s)   ((s) * 5120)              // 64 rows x 80B (40 fp16, padded)
#define LDA1BY   80
#define B1B(s)   (15360 + (s) * 8192)
#define B2B(s)   ((s) * 6144)
#define WOFB     25600                      // 4KB wo fragments
#define GSB      0                          // fp32 64 x 50
#define LDGS     50
#define YHB      12800                      // fp16 64 x 24
#define LDYBY    48
#define H1HB     39936                      // fp16 64 x 136 (272B rows)
#define LDHBY    272
#define S2B      57344                      // fp32 64 x 132
#define LDS2     132
#define B1BB     91136                      // fp32 b1[128]
#define B2EB     91648                      // fp32 b2e[192]
#define BOBB     92416                      // fp32 bo[128]
#define SMEM_BYTES 92928                    // ~90.8 KB -> 2 CTAs/SM

// ---------------- device-global prepped weights (fp16 fragment order) ----------------
// GEMM1 B frags: [kc(12)][ks(2)][wn(4)][p(2)][lane(32)] x uint4
__device__ __align__(16) unsigned g_w1f[6144 * 4];
// intermediate w2ext^T fp32 [n(192)][k(128)] (n>=176 zero)
__device__ __align__(16) float g_w2e[192 * 128];
__device__ float g_b2e[192];
// GEMM2 B frags: [kc(8 k16)][wn(4)][p(3)][lane(32)] x uint4
__device__ __align__(16) unsigned g_w2f[3072 * 4];
// GEMM3 wo frags: [wn(2)][p(4)][lane(32)] x uint4
__device__ __align__(16) unsigned g_wof[256 * 4];

// ---------------- helpers ----------------
__device__ __forceinline__ unsigned packh(float lo, float hi) {
    __half2 h = __halves2half2(__float2half_rn(lo), __float2half_rn(hi));
    return *(unsigned*)&h;
}
__device__ __forceinline__ uint32_t smem_u32(const void* p) {
    uint32_t a;
    asm("{ .reg .u64 t; cvta.to.shared.u64 t, %1; cvt.u32.u64 %0, t; }" : "=r"(a) : "l"(p));
    return a;
}
__device__ __forceinline__ void cp16(uint32_t s, const void* g) {
    asm volatile("cp.async.cg.shared.global [%0], [%1], 16;" :: "r"(s), "l"(g));
}
#define CP_COMMIT() asm volatile("cp.async.commit_group;" ::: "memory")
#define CP_WAIT(n)  asm volatile("cp.async.wait_group %0;" :: "n"(n) : "memory")

__device__ __forceinline__ void mma16(float* c, const unsigned* a, unsigned b0, unsigned b1) {
    asm volatile(
        "mma.sync.aligned.m16n8k16.row.col.f32.f16.f16.f32 "
        "{%0,%1,%2,%3}, {%4,%5,%6,%7}, {%8,%9}, {%0,%1,%2,%3};"
        : "+f"(c[0]), "+f"(c[1]), "+f"(c[2]), "+f"(c[3])
        : "r"(a[0]), "r"(a[1]), "r"(a[2]), "r"(a[3]), "r"(b0), "r"(b1));
}

// ---------------- prep kernels ----------------
__global__ void prep_w2e(const float* __restrict__ w2, const float* __restrict__ b2,
                         const float* __restrict__ wg, const float* __restrict__ bg,
                         const float* __restrict__ wt, const float* __restrict__ bt,
                         const float* __restrict__ wp, const float* __restrict__ bp) {
    int n = blockIdx.x;     // 0..191
    int k = threadIdx.x;    // 0..127
    float v = 0.f, b = 0.f;
    if (n < 128) {
        v = w2[k * 128 + n];
        b = b2[n];
    } else if (n < 176) {
        int p = (n - 128) >> 4, j = (n - 128) & 15;
        const float* W = (p == 0) ? wg : (p == 1) ? wt : wp;
        const float* B = (p == 0) ? bg : (p == 1) ? bt : bp;
        float s = 0.f;
        for (int m = 0; m < 128; m++) s += w2[k * 128 + m] * W[m * 16 + j];
        v = s;
        float sb = B[j];
        for (int m = 0; m < 128; m++) sb += b2[m] * W[m * 16 + j];
        b = sb;
    }
    g_w2e[n * 128 + k] = v;
    if (k == 0) g_b2e[n] = b;
}

// w1[k(384)][n(128)] -> fp16 frag order [kc(12)][ks(2)][wn(4)][p(2)][lane]
__global__ void prep_w1f(const float* __restrict__ w1) {
    int u = blockIdx.x * 128 + threadIdx.x;   // 0..6143
    int lane = u & 31;
    int r = u >> 5;                            // 0..191
    int p  = r & 1;
    int wn = (r >> 1) & 3;
    int ks = (r >> 3) & 1;
    int kc = r >> 4;
    int n0 = wn * 32 + p * 16 + (lane >> 2);
    int kb = kc * 32 + ks * 16 + 2 * (lane & 3);
    unsigned* o = g_w1f + u * 4;
    o[0] = packh(w1[kb * 128 + n0],       w1[(kb + 1) * 128 + n0]);
    o[1] = packh(w1[(kb + 8) * 128 + n0], w1[(kb + 9) * 128 + n0]);
    o[2] = packh(w1[kb * 128 + n0 + 8],       w1[(kb + 1) * 128 + n0 + 8]);
    o[3] = packh(w1[(kb + 8) * 128 + n0 + 8], w1[(kb + 9) * 128 + n0 + 8]);
}

// g_w2e[n][k] -> fp16 frag order [kc(8 k16)][wn(4)][p(3)][lane]
__global__ void prep_w2f() {
    int u = blockIdx.x * 128 + threadIdx.x;   // 0..3071
    int lane = u & 31;
    int r = u >> 5;                            // 0..95
    int p = r % 3; r /= 3;                     // 0..31
    int wn = r & 3;
    int kc = r >> 2;                           // 0..7
    int n0 = wn * 48 + p * 16 + (lane >> 2);
    int kb = kc * 16 + 2 * (lane & 3);
    unsigned* o = g_w2f + u * 4;
    o[0] = packh(g_w2e[n0 * 128 + kb],     g_w2e[n0 * 128 + kb + 1]);
    o[1] = packh(g_w2e[n0 * 128 + kb + 8], g_w2e[n0 * 128 + kb + 9]);
    o[2] = packh(g_w2e[(n0 + 8) * 128 + kb],     g_w2e[(n0 + 8) * 128 + kb + 1]);
    o[3] = packh(g_w2e[(n0 + 8) * 128 + kb + 8], g_w2e[(n0 + 8) * 128 + kb + 9]);
}

// wo[k(16)][n(128)] -> fp16 frag order [wn(2)][p(4)][lane]
__global__ void prep_wof(const float* __restrict__ wo) {
    int u = blockIdx.x * 128 + threadIdx.x;   // 0..255
    int lane = u & 31;
    int r = u >> 5;                            // 0..7
    int p  = r & 3;
    int wn = r >> 2;
    int n0 = wn * 64 + p * 16 + (lane >> 2);
    int kb = 2 * (lane & 3);
    unsigned* o = g_wof + u * 4;
    o[0] = packh(wo[kb * 128 + n0],       wo[(kb + 1) * 128 + n0]);
    o[1] = packh(wo[(kb + 8) * 128 + n0], wo[(kb + 9) * 128 + n0]);
    o[2] = packh(wo[kb * 128 + n0 + 8],       wo[(kb + 1) * 128 + n0 + 8]);
    o[3] = packh(wo[(kb + 8) * 128 + n0 + 8], wo[(kb + 9) * 128 + n0 + 8]);
}

// ---------------- main fused kernel: 64 edges/CTA, 256 threads, 2 CTA/SM ----------------
extern __shared__ char smc[];

__global__ void __launch_bounds__(NTH, 2)
edge_att_kernel(const float* __restrict__ src, const float* __restrict__ tgt,
                const float* __restrict__ ea,
                const float* __restrict__ b1v, const float* __restrict__ bo,
                float* __restrict__ out) {
    const int tid  = threadIdx.x;
    const int lane = tid & 31;
    const int wid  = tid >> 5;       // 8 warps
    const int wm   = wid & 1;        // 2 M-warps (32 rows each)
    const int wn   = wid >> 1;       // 4 N-warps
    const int row0 = wm * 32;
    const long e0  = (long)blockIdx.x * TILE_M;
    const uint32_t sbase = smem_u32(smc);
    float* smf = (float*)smc;

    // persistent biases (fp32)
    if (tid < 128) smf[B1BB / 4 + tid] = b1v[tid];
    if (tid < 128) smf[BOBB / 4 + tid] = bo[tid];
    if (tid < 192) smf[B2EB / 4 + tid] = g_b2e[tid];

    // ---- staging lambdas ----
    auto ldgA = [&](int kc, float4* pr) {
        const float* sp = (kc < 4) ? src : (kc < 8) ? tgt : ea;
        int cin = (kc & 3) * 32;
#pragma unroll
        for (int i = 0; i < 2; i++) {
            int f = tid + i * NTH;           // 0..511
            int r = f >> 3, c4 = f & 7;
            long e = e0 + r; if (e >= E_TOTAL) e = E_TOTAL - 1;
            pr[i] = *(const float4*)(sp + e * 128 + cin + c4 * 4);
        }
    };
    auto stsA = [&](int kc, const float4* pr) {
        char* base = smc + A1B(kc % 3);
#pragma unroll
        for (int i = 0; i < 2; i++) {
            int f = tid + i * NTH;
            int r = f >> 3, c4 = f & 7;
            uint2 h;
            h.x = packh(pr[i].x, pr[i].y);
            h.y = packh(pr[i].z, pr[i].w);
            *(uint2*)(base + r * LDA1BY + c4 * 8) = h;
        }
    };
    auto cpB1 = [&](int kc) {
        uint32_t sb = sbase + B1B(kc % 3);
#pragma unroll
        for (int i = 0; i < 2; i++) {
            int f = tid + i * NTH;           // 512 x 16B = 8KB
            cp16(sb + f * 16, g_w1f + (kc * 512 + f) * 4);
        }
    };
    auto cpB2 = [&](int kc) {
        uint32_t sb = sbase + B2B(kc & 3);
        {
            int f = tid;                      // 384 x 16B = 6KB
            if (f < 384) cp16(sb + f * 16, g_w2f + (kc * 384 + f) * 4);
        }
#pragma unroll
        for (int i = 1; i < 2; i++) {
            int f = tid + i * NTH;
            if (f < 384) cp16(sb + f * 16, g_w2f + (kc * 384 + f) * 4);
        }
    };
    auto cpWOF = [&]() {
        if (tid < 256) cp16(sbase + WOFB + tid * 16, g_wof + tid * 4);
    };

    // ================= GEMM1: H1 = relu(X @ w1 + b1), K=384 (12 x k32) ================
    float acc1[2][4][4];
#pragma unroll
    for (int mt = 0; mt < 2; mt++)
#pragma unroll
        for (int nt = 0; nt < 4; nt++)
#pragma unroll
            for (int q = 0; q < 4; q++) acc1[mt][nt][q] = 0.f;

    float4 pa[2][2];
    ldgA(0, pa[0]); stsA(0, pa[0]);
    ldgA(1, pa[1]);
    cpB1(0); CP_COMMIT();
    cpB1(1); CP_COMMIT();

#pragma unroll
    for (int kc = 0; kc < 12; kc++) {
        CP_WAIT(1);
        __syncthreads();
        if (kc + 2 < 12) { cpB1(kc + 2); ldgA(kc + 2, pa[kc & 1]); }
        CP_COMMIT();

        const char* Ab = smc + A1B(kc % 3);
        const uint4* Bb = (const uint4*)(smc + B1B(kc % 3));
#pragma unroll
        for (int ks = 0; ks < 2; ks++) {
            int r = row0 + (lane >> 2);
            int cb = ks * 32 + (lane & 3) * 4;
            unsigned a0[4], a1[4];
            a0[0] = *(const unsigned*)(Ab + r * LDA1BY + cb);
            a0[1] = *(const unsigned*)(Ab + (r + 8) * LDA1BY + cb);
            a0[2] = *(const unsigned*)(Ab + r * LDA1BY + cb + 16);
            a0[3] = *(const unsigned*)(Ab + (r + 8) * LDA1BY + cb + 16);
            a1[0] = *(const unsigned*)(Ab + (r + 16) * LDA1BY + cb);
            a1[1] = *(const unsigned*)(Ab + (r + 24) * LDA1BY + cb);
            a1[2] = *(const unsigned*)(Ab + (r + 16) * LDA1BY + cb + 16);
            a1[3] = *(const unsigned*)(Ab + (r + 24) * LDA1BY + cb + 16);
#pragma unroll
            for (int p = 0; p < 2; p++) {
                uint4 bv = Bb[(ks * 8 + wn * 2 + p) * 32 + lane];
                mma16(acc1[0][2 * p],     a0, bv.x, bv.y);
                mma16(acc1[0][2 * p + 1], a0, bv.z, bv.w);
                mma16(acc1[1][2 * p],     a1, bv.x, bv.y);
                mma16(acc1[1][2 * p + 1], a1, bv.z, bv.w);
            }
        }
        if (kc + 1 < 12) stsA(kc + 1, pa[(kc + 1) & 1]);
    }

    // ---- epilogue 1: H1h = fp16(relu(acc + b1)) ----
    {
        const int col0 = wn * 32;
#pragma unroll
        for (int mt = 0; mt < 2; mt++)
#pragma unroll
            for (int nt = 0; nt < 4; nt++) {
                int r = row0 + mt * 16 + (lane >> 2);
                int c = col0 + nt * 8 + (lane & 3) * 2;
                float bb0 = smf[B1BB / 4 + c], bb1 = smf[B1BB / 4 + c + 1];
                *(unsigned*)(smc + H1HB + r * LDHBY + c * 2) =
                    packh(fmaxf(acc1[mt][nt][0] + bb0, 0.f), fmaxf(acc1[mt][nt][1] + bb1, 0.f));
                *(unsigned*)(smc + H1HB + (r + 8) * LDHBY + c * 2) =
                    packh(fmaxf(acc1[mt][nt][2] + bb0, 0.f), fmaxf(acc1[mt][nt][3] + bb1, 0.f));
            }
    }
    __syncthreads();   // H1h visible; GEMM1 rings retired

    // ================= GEMM2: [H2|G|TH|PH|pad] = H1 @ w2ext, N=192, K=128 (8 x k16) ===
    float acc2[2][6][4];
#pragma unroll
    for (int mt = 0; mt < 2; mt++)
#pragma unroll
        for (int nt = 0; nt < 6; nt++)
#pragma unroll
            for (int q = 0; q < 4; q++) acc2[mt][nt][q] = 0.f;

    cpWOF(); cpB2(0); CP_COMMIT();
    cpB2(1); CP_COMMIT();
    cpB2(2); CP_COMMIT();

#pragma unroll
    for (int kc = 0; kc < 8; kc++) {
        CP_WAIT(2);
        __syncthreads();
        if (kc + 3 < 8) cpB2(kc + 3);
        CP_COMMIT();

        const uint4* Bb = (const uint4*)(smc + B2B(kc & 3));
        int r = row0 + (lane >> 2);
        int cb = kc * 32 + (lane & 3) * 4;
        unsigned a0[4], a1[4];
        a0[0] = *(const unsigned*)(smc + H1HB + r * LDHBY + cb);
        a0[1] = *(const unsigned*)(smc + H1HB + (r + 8) * LDHBY + cb);
        a0[2] = *(const unsigned*)(smc + H1HB + r * LDHBY + cb + 16);
        a0[3] = *(const unsigned*)(smc + H1HB + (r + 8) * LDHBY + cb + 16);
        a1[0] = *(const unsigned*)(smc + H1HB + (r + 16) * LDHBY + cb);
        a1[1] = *(const unsigned*)(smc + H1HB + (r + 24) * LDHBY + cb);
        a1[2] = *(const unsigned*)(smc + H1HB + (r + 16) * LDHBY + cb + 16);
        a1[3] = *(const unsigned*)(smc + H1HB + (r + 24) * LDHBY + cb + 16);
#pragma unroll
        for (int p = 0; p < 3; p++) {
            uint4 bv = Bb[(wn * 3 + p) * 32 + lane];
            mma16(acc2[0][2 * p],     a0, bv.x, bv.y);
            mma16(acc2[0][2 * p + 1], a0, bv.z, bv.w);
            mma16(acc2[1][2 * p],     a1, bv.x, bv.y);
            mma16(acc2[1][2 * p + 1], a1, bv.z, bv.w);
        }
    }
    __syncthreads();   // all H1h/B2 reads done -> safe to overlay GS/Y and write S2

    // ---- epilogue 2: S2 fp32 (cols<128); GS fp32 (128..175) ----
#pragma unroll
    for (int mt = 0; mt < 2; mt++)
#pragma unroll
        for (int nt = 0; nt < 6; nt++) {
            int r = row0 + mt * 16 + (lane >> 2);
            int c = wn * 48 + nt * 8 + (lane & 3) * 2;
            float bb0 = smf[B2EB / 4 + c], bb1 = smf[B2EB / 4 + c + 1];
            float v0 = acc2[mt][nt][0] + bb0, v1 = acc2[mt][nt][1] + bb1;
            float v2 = acc2[mt][nt][2] + bb0, v3 = acc2[mt][nt][3] + bb1;
            if (c < 128) {
                *(float2*)&smf[S2B / 4 + r * LDS2 + c]       = make_float2(v0, v1);
                *(float2*)&smf[S2B / 4 + (r + 8) * LDS2 + c] = make_float2(v2, v3);
            } else if (c < 176) {
                int cc = c - 128;
                *(float2*)&smf[GSB / 4 + r * LDGS + cc]       = make_float2(v0, v1);
                *(float2*)&smf[GSB / 4 + (r + 8) * LDGS + cc] = make_float2(v2, v3);
            }
        }
    __syncthreads();

    // ================= attention softmax: Y[r][i] = softmax_j(ph_i*th_j) . g ==========
    {
        int r = tid >> 2;                  // 0..63
        int i0 = (tid & 3) * 4;
        const float* srow = &smf[GSB / 4 + r * LDGS];
        float gg[16], th[16];
#pragma unroll
        for (int j = 0; j < 16; j++) { gg[j] = srow[j]; th[j] = srow[16 + j]; }
        float yv[4];
#pragma unroll
        for (int q = 0; q < 4; q++) {
            float ph = srow[32 + i0 + q];
            float m = ph * th[0];
#pragma unroll
            for (int j = 1; j < 16; j++) m = fmaxf(m, ph * th[j]);
            float s = 0.f, ys = 0.f;
#pragma unroll
            for (int j = 0; j < 16; j++) {
                float e = __expf(ph * th[j] - m);
                s += e; ys += e * gg[j];
            }
            yv[q] = ys / s;
        }
        uint2 h;
        h.x = packh(yv[0], yv[1]);
        h.y = packh(yv[2], yv[3]);
        *(uint2*)(smc + YHB + r * LDYBY + i0 * 2) = h;
    }
    CP_WAIT(0);        // wo fragments resident
    __syncthreads();

    // ================= GEMM3: OUT = Y @ wo + bo + H2 (residual), K=16 =================
    {
        const int row0g = (wid & 3) * 16;
        const int wn3   = wid >> 2;
        const int col0g = wn3 * 64;
        const uint4* Wf = (const uint4*)(smc + WOFB);
        float acc3[8][4];
#pragma unroll
        for (int nt = 0; nt < 8; nt++)
#pragma unroll
            for (int q = 0; q < 4; q++) acc3[nt][q] = 0.f;

        unsigned a[4];
        {
            int r = row0g + (lane >> 2);
            int cb = (lane & 3) * 4;
            a[0] = *(const unsigned*)(smc + YHB + r * LDYBY + cb);
            a[1] = *(const unsigned*)(smc + YHB + (r + 8) * LDYBY + cb);
            a[2] = *(const unsigned*)(smc + YHB + r * LDYBY + cb + 16);
            a[3] = *(const unsigned*)(smc + YHB + (r + 8) * LDYBY + cb + 16);
        }
#pragma unroll
        for (int p = 0; p < 4; p++) {
            uint4 bv = Wf[(wn3 * 4 + p) * 32 + lane];
            mma16(acc3[2 * p],     a, bv.x, bv.y);
            mma16(acc3[2 * p + 1], a, bv.z, bv.w);
        }

#pragma unroll
        for (int nt = 0; nt < 8; nt++) {
            int r = row0g + (lane >> 2);
            int c = col0g + nt * 8 + (lane & 3) * 2;
            float bb0 = smf[BOBB / 4 + c], bb1 = smf[BOBB / 4 + c + 1];
            long e = e0 + r;
            if (e < E_TOTAL) {
                float o0 = acc3[nt][0] + smf[S2B / 4 + r * LDS2 + c] + bb0;
                float o1 = acc3[nt][1] + smf[S2B / 4 + r * LDS2 + c + 1] + bb1;
                *(float2*)&out[e * 128 + c] = make_float2(o0, o1);
            }
            long e2 = e + 8;
            if (e2 < E_TOTAL) {
                float o2 = acc3[nt][2] + smf[S2B / 4 + (r + 8) * LDS2 + c] + bb0;
                float o3 = acc3[nt][3] + smf[S2B / 4 + (r + 8) * LDS2 + c + 1] + bb1;
                *(float2*)&out[e2 * 128 + c] = make_float2(o2, o3);
            }
        }
    }
}

extern "C" void kernel_launch(void* const* d_in, const int* in_sizes, int n_in,
                              void* d_out, int out_size) {
    const float* src = (const float*)d_in[0];
    const float* tgt = (const float*)d_in[1];
    const float* ea  = (const float*)d_in[2];
    const float* w1  = (const float*)d_in[3];
    const float* b1  = (const float*)d_in[4];
    const float* w2  = (const float*)d_in[5];
    const float* b2  = (const float*)d_in[6];
    const float* wg  = (const float*)d_in[7];
    const float* bg  = (const float*)d_in[8];
    const float* wt  = (const float*)d_in[9];
    const float* bt  = (const float*)d_in[10];
    const float* wp  = (const float*)d_in[11];
    const float* bp  = (const float*)d_in[12];
    const float* wo  = (const float*)d_in[13];
    const float* bo  = (const float*)d_in[14];
    float* out = (float*)d_out;

    cudaFuncSetAttribute(edge_att_kernel,
                         cudaFuncAttributeMaxDynamicSharedMemorySize, SMEM_BYTES);

    prep_w2e<<<192, 128>>>(w2, b2, wg, bg, wt, bt, wp, bp);
    prep_w1f<<<48, 128>>>(w1);
    prep_w2f<<<24, 128>>>();
    prep_wof<<<2, 128>>>(wo);

    int grid = (E_TOTAL + TILE_M - 1) / TILE_M;   // 4688
    edge_att_kernel<<<grid, NTH, SMEM_BYTES>>>(src, tgt, ea, b1, bo, out);
}

// round 8
// speedup vs baseline: 2.1623x; 1.0044x over previous
#include <cuda_runtime.h>
#include <cuda_fp16.h>
#include <cstdint>

#define E_TOTAL 300000
#define TILE_M  64
#define NTH     256

// ---------------- shared memory byte offsets ----------------
#define A1B(s)   ((s) * 9216)               // 64 rows x 144B (64 fp16 + pad16)
#define LDA1BY   144
#define B1B(s)   (27648 + (s) * 16384)      // 3 stages, end 76800
#define B2B(s)   ((s) * 12288)              // 3 stages, end 36864 (overlay phase-1)
#define WOFB     36864                       // 4KB
#define GSB      40960                       // fp32 64 x 50
#define LDGS     50
#define YHB      53760                       // fp16 64 x 24 (48B rows)
#define LDYBY    48
#define H1HB     76800                       // fp16 64 x 136 (272B rows)
#define LDHBY    272
#define S2B      76800                       // fp32 64 x 132 (overlays H1 after GEMM2)
#define LDS2     132
#define B1BB     110592                      // fp32 b1[128]
#define B2EB     111104                      // fp32 b2e[192]
#define BOBB     111872                      // fp32 bo[128]
#define SMEM_BYTES 112384                    // 2 CTAs/SM

// ---------------- device-global prepped weights (fp16 fragment order) ----------------
// GEMM1 B frags: [kc(6,k64)][ks(4)][wn(4)][p(2)][lane(32)] x uint4
__device__ __align__(16) unsigned g_w1f[6144 * 4];
// intermediate w2ext^T fp32 [n(192)][k(128)] (n>=176 zero)
__device__ __align__(16) float g_w2e[192 * 128];
__device__ float g_b2e[192];
// GEMM2 B frags: [kc(4,k32)][ks(2)][wn(4)][p(3)][lane(32)] x uint4
__device__ __align__(16) unsigned g_w2f[3072 * 4];
// GEMM3 wo frags: [wn(2)][p(4)][lane(32)] x uint4
__device__ __align__(16) unsigned g_wof[256 * 4];

// ---------------- helpers ----------------
__device__ __forceinline__ unsigned packh(float lo, float hi) {
    __half2 h = __halves2half2(__float2half_rn(lo), __float2half_rn(hi));
    return *(unsigned*)&h;
}
__device__ __forceinline__ uint32_t smem_u32(const void* p) {
    uint32_t a;
    asm("{ .reg .u64 t; cvta.to.shared.u64 t, %1; cvt.u32.u64 %0, t; }" : "=r"(a) : "l"(p));
    return a;
}
__device__ __forceinline__ void cp16(uint32_t s, const void* g) {
    asm volatile("cp.async.cg.shared.global [%0], [%1], 16;" :: "r"(s), "l"(g));
}
#define CP_COMMIT() asm volatile("cp.async.commit_group;" ::: "memory")
#define CP_WAIT(n)  asm volatile("cp.async.wait_group %0;" :: "n"(n) : "memory")

__device__ __forceinline__ void ldsm4(unsigned* d, uint32_t addr) {
    asm volatile("ldmatrix.sync.aligned.m8n8.x4.shared.b16 {%0,%1,%2,%3}, [%4];"
                 : "=r"(d[0]), "=r"(d[1]), "=r"(d[2]), "=r"(d[3]) : "r"(addr));
}
__device__ __forceinline__ void mma16(float* c, const unsigned* a, unsigned b0, unsigned b1) {
    asm volatile(
        "mma.sync.aligned.m16n8k16.row.col.f32.f16.f16.f32 "
        "{%0,%1,%2,%3}, {%4,%5,%6,%7}, {%8,%9}, {%0,%1,%2,%3};"
        : "+f"(c[0]), "+f"(c[1]), "+f"(c[2]), "+f"(c[3])
        : "r"(a[0]), "r"(a[1]), "r"(a[2]), "r"(a[3]), "r"(b0), "r"(b1));
}

// ---------------- prep kernels ----------------
__global__ void prep_w2e(const float* __restrict__ w2, const float* __restrict__ b2,
                         const float* __restrict__ wg, const float* __restrict__ bg,
                         const float* __restrict__ wt, const float* __restrict__ bt,
                         const float* __restrict__ wp, const float* __restrict__ bp) {
    int n = blockIdx.x;     // 0..191
    int k = threadIdx.x;    // 0..127
    float v = 0.f, b = 0.f;
    if (n < 128) {
        v = w2[k * 128 + n];
        b = b2[n];
    } else if (n < 176) {
        int p = (n - 128) >> 4, j = (n - 128) & 15;
        const float* W = (p == 0) ? wg : (p == 1) ? wt : wp;
        const float* B = (p == 0) ? bg : (p == 1) ? bt : bp;
        float s = 0.f;
        for (int m = 0; m < 128; m++) s += w2[k * 128 + m] * W[m * 16 + j];
        v = s;
        float sb = B[j];
        for (int m = 0; m < 128; m++) sb += b2[m] * W[m * 16 + j];
        b = sb;
    }
    g_w2e[n * 128 + k] = v;
    if (k == 0) g_b2e[n] = b;
}

// w1[k(384)][n(128)] -> fp16 frag order [kc(6)][ks(4)][wn(4)][p(2)][lane]
__global__ void prep_w1f(const float* __restrict__ w1) {
    int u = blockIdx.x * 128 + threadIdx.x;   // 0..6143
    int lane = u & 31;
    int r = u >> 5;                            // 0..191
    int p  = r & 1;
    int wn = (r >> 1) & 3;
    int ks = (r >> 3) & 3;
    int kc = r >> 5;                           // 0..5
    int n0 = wn * 32 + p * 16 + (lane >> 2);
    int kb = kc * 64 + ks * 16 + 2 * (lane & 3);
    unsigned* o = g_w1f + u * 4;
    o[0] = packh(w1[kb * 128 + n0],       w1[(kb + 1) * 128 + n0]);
    o[1] = packh(w1[(kb + 8) * 128 + n0], w1[(kb + 9) * 128 + n0]);
    o[2] = packh(w1[kb * 128 + n0 + 8],       w1[(kb + 1) * 128 + n0 + 8]);
    o[3] = packh(w1[(kb + 8) * 128 + n0 + 8], w1[(kb + 9) * 128 + n0 + 8]);
}

// g_w2e[n][k] -> fp16 frag order [kc(4,k32)][ks(2)][wn(4)][p(3)][lane]
__global__ void prep_w2f() {
    int u = blockIdx.x * 128 + threadIdx.x;   // 0..3071
    int lane = u & 31;
    int r = u >> 5;                            // 0..95
    int p = r % 3; r /= 3;                     // 0..31
    int wn = r & 3;
    int ks = (r >> 2) & 1;
    int kc = r >> 3;                           // 0..3
    int n0 = wn * 48 + p * 16 + (lane >> 2);
    int kb = kc * 32 + ks * 16 + 2 * (lane & 3);
    unsigned* o = g_w2f + u * 4;
    o[0] = packh(g_w2e[n0 * 128 + kb],     g_w2e[n0 * 128 + kb + 1]);
    o[1] = packh(g_w2e[n0 * 128 + kb + 8], g_w2e[n0 * 128 + kb + 9]);
    o[2] = packh(g_w2e[(n0 + 8) * 128 + kb],     g_w2e[(n0 + 8) * 128 + kb + 1]);
    o[3] = packh(g_w2e[(n0 + 8) * 128 + kb + 8], g_w2e[(n0 + 8) * 128 + kb + 9]);
}

// wo[k(16)][n(128)] -> fp16 frag order [wn(2)][p(4)][lane]
__global__ void prep_wof(const float* __restrict__ wo) {
    int u = blockIdx.x * 128 + threadIdx.x;   // 0..255
    int lane = u & 31;
    int r = u >> 5;                            // 0..7
    int p  = r & 3;
    int wn = r >> 2;
    int n0 = wn * 64 + p * 16 + (lane >> 2);
    int kb = 2 * (lane & 3);
    unsigned* o = g_wof + u * 4;
    o[0] = packh(wo[kb * 128 + n0],       wo[(kb + 1) * 128 + n0]);
    o[1] = packh(wo[(kb + 8) * 128 + n0], wo[(kb + 9) * 128 + n0]);
    o[2] = packh(wo[kb * 128 + n0 + 8],       wo[(kb + 1) * 128 + n0 + 8]);
    o[3] = packh(wo[(kb + 8) * 128 + n0 + 8], wo[(kb + 9) * 128 + n0 + 8]);
}

// ---------------- main fused kernel: 64 edges/CTA, 256 threads, 2 CTA/SM ----------------
extern __shared__ char smc[];

__global__ void __launch_bounds__(NTH, 2)
edge_att_kernel(const float* __restrict__ src, const float* __restrict__ tgt,
                const float* __restrict__ ea,
                const float* __restrict__ b1v, const float* __restrict__ bo,
                float* __restrict__ out) {
    const int tid  = threadIdx.x;
    const int lane = tid & 31;
    const int wid  = tid >> 5;       // 8 warps
    const int wm   = wid & 1;        // 2 M-warps (32 rows each)
    const int wn   = wid >> 1;       // 4 N-warps
    const int row0 = wm * 32;
    const long e0  = (long)blockIdx.x * TILE_M;
    const uint32_t sbase = smem_u32(smc);
    float* smf = (float*)smc;

    // persistent biases (fp32)
    if (tid < 128) smf[B1BB / 4 + tid] = b1v[tid];
    if (tid < 128) smf[BOBB / 4 + tid] = bo[tid];
    if (tid < 192) smf[B2EB / 4 + tid] = g_b2e[tid];

    // ---- staging lambdas ----
    auto ldgA = [&](int kc, float4* pr) {     // k64 chunk: 64 rows x 64 fp32
        const float* sp = (kc < 2) ? src : (kc < 4) ? tgt : ea;
        int cin = (kc & 1) * 64;
#pragma unroll
        for (int i = 0; i < 4; i++) {
            int f = tid + i * NTH;            // 0..1023
            int r = f >> 4, c4 = f & 15;
            long e = e0 + r; if (e >= E_TOTAL) e = E_TOTAL - 1;
            pr[i] = *(const float4*)(sp + e * 128 + cin + c4 * 4);
        }
    };
    auto stsA = [&](int kc, const float4* pr) {
        char* base = smc + A1B(kc % 3);
#pragma unroll
        for (int i = 0; i < 4; i++) {
            int f = tid + i * NTH;
            int r = f >> 4, c4 = f & 15;
            uint2 h;
            h.x = packh(pr[i].x, pr[i].y);
            h.y = packh(pr[i].z, pr[i].w);
            *(uint2*)(base + r * LDA1BY + c4 * 8) = h;
        }
    };
    auto cpB1 = [&](int kc) {                 // 1024 uint4 = 16KB
        uint32_t sb = sbase + B1B(kc % 3);
#pragma unroll
        for (int i = 0; i < 4; i++) {
            int f = tid + i * NTH;
            cp16(sb + f * 16, g_w1f + (kc * 1024 + f) * 4);
        }
    };
    auto cpB2 = [&](int kc) {                 // 768 uint4 = 12KB
        uint32_t sb = sbase + B2B(kc % 3);
#pragma unroll
        for (int i = 0; i < 3; i++) {
            int f = tid + i * NTH;
            cp16(sb + f * 16, g_w2f + (kc * 768 + f) * 4);
        }
    };
    auto cpWOF = [&]() {
        cp16(sbase + WOFB + tid * 16, g_wof + tid * 4);
    };

    // ================= GEMM1: H1 = relu(X @ w1 + b1), K=384 (6 x k64) =================
    float acc1[2][4][4];
#pragma unroll
    for (int mt = 0; mt < 2; mt++)
#pragma unroll
        for (int nt = 0; nt < 4; nt++)
#pragma unroll
            for (int q = 0; q < 4; q++) acc1[mt][nt][q] = 0.f;

    float4 pa[4];
    ldgA(0, pa); stsA(0, pa);
    ldgA(1, pa);
    cpB1(0); CP_COMMIT();
    cpB1(1); CP_COMMIT();

#pragma unroll
    for (int kc = 0; kc < 6; kc++) {
        CP_WAIT(1);
        __syncthreads();
        if (kc + 2 < 6) cpB1(kc + 2);
        CP_COMMIT();

        const uint32_t Ab = sbase + A1B(kc % 3);
        const uint4* Bb = (const uint4*)(smc + B1B(kc % 3));
#pragma unroll
        for (int ks = 0; ks < 4; ks++) {
            unsigned a0[4], a1[4];
            uint32_t ab = Ab + (row0 + (lane & 15)) * LDA1BY + ((lane >> 4) << 4) + ks * 32;
            ldsm4(a0, ab);
            ldsm4(a1, ab + 16 * LDA1BY);
#pragma unroll
            for (int p = 0; p < 2; p++) {
                uint4 bv = Bb[(ks * 8 + wn * 2 + p) * 32 + lane];
                mma16(acc1[0][2 * p],     a0, bv.x, bv.y);
                mma16(acc1[0][2 * p + 1], a0, bv.z, bv.w);
                mma16(acc1[1][2 * p],     a1, bv.x, bv.y);
                mma16(acc1[1][2 * p + 1], a1, bv.z, bv.w);
            }
        }
        if (kc + 1 < 6) stsA(kc + 1, pa);
        if (kc + 2 < 6) ldgA(kc + 2, pa);
    }

    // ---- epilogue 1: H1h = fp16(relu(acc + b1)), stride 272B (conflict-free) ----
    {
        const int col0 = wn * 32;
#pragma unroll
        for (int mt = 0; mt < 2; mt++)
#pragma unroll
            for (int nt = 0; nt < 4; nt++) {
                int r = row0 + mt * 16 + (lane >> 2);
                int c = col0 + nt * 8 + (lane & 3) * 2;
                float bb0 = smf[B1BB / 4 + c], bb1 = smf[B1BB / 4 + c + 1];
                *(unsigned*)(smc + H1HB + r * LDHBY + c * 2) =
                    packh(fmaxf(acc1[mt][nt][0] + bb0, 0.f), fmaxf(acc1[mt][nt][1] + bb1, 0.f));
                *(unsigned*)(smc + H1HB + (r + 8) * LDHBY + c * 2) =
                    packh(fmaxf(acc1[mt][nt][2] + bb0, 0.f), fmaxf(acc1[mt][nt][3] + bb1, 0.f));
            }
    }
    __syncthreads();   // H1h visible; GEMM1 rings retired

    // ================= GEMM2: [H2|G|TH|PH|pad] = H1 @ w2ext, N=192, K=128 (4 x k32) ===
    float acc2[2][6][4];
#pragma unroll
    for (int mt = 0; mt < 2; mt++)
#pragma unroll
        for (int nt = 0; nt < 6; nt++)
#pragma unroll
            for (int q = 0; q < 4; q++) acc2[mt][nt][q] = 0.f;

    cpWOF(); cpB2(0); CP_COMMIT();
    cpB2(1); CP_COMMIT();

#pragma unroll
    for (int kc = 0; kc < 4; kc++) {
        CP_WAIT(1);
        __syncthreads();
        if (kc + 2 < 4) cpB2(kc + 2);
        CP_COMMIT();

        const uint4* Bb = (const uint4*)(smc + B2B(kc % 3));
#pragma unroll
        for (int ks = 0; ks < 2; ks++) {
            unsigned a0[4], a1[4];
            uint32_t ab = sbase + H1HB + (row0 + (lane & 15)) * LDHBY +
                          ((lane >> 4) << 4) + kc * 64 + ks * 32;
            ldsm4(a0, ab);
            ldsm4(a1, ab + 16 * LDHBY);
#pragma unroll
            for (int p = 0; p < 3; p++) {
                uint4 bv = Bb[(ks * 12 + wn * 3 + p) * 32 + lane];
                mma16(acc2[0][2 * p],     a0, bv.x, bv.y);
                mma16(acc2[0][2 * p + 1], a0, bv.z, bv.w);
                mma16(acc2[1][2 * p],     a1, bv.x, bv.y);
                mma16(acc2[1][2 * p + 1], a1, bv.z, bv.w);
            }
        }
    }
    __syncthreads();   // all H1h/B2 reads done -> safe to write S2 (overlays H1)

    // ---- epilogue 2: S2 fp32 (cols<128); GS fp32 (128..175) ----
#pragma unroll
    for (int mt = 0; mt < 2; mt++)
#pragma unroll
        for (int nt = 0; nt < 6; nt++) {
            int r = row0 + mt * 16 + (lane >> 2);
            int c = wn * 48 + nt * 8 + (lane & 3) * 2;
            float bb0 = smf[B2EB / 4 + c], bb1 = smf[B2EB / 4 + c + 1];
            float v0 = acc2[mt][nt][0] + bb0, v1 = acc2[mt][nt][1] + bb1;
            float v2 = acc2[mt][nt][2] + bb0, v3 = acc2[mt][nt][3] + bb1;
            if (c < 128) {
                *(float2*)&smf[S2B / 4 + r * LDS2 + c]       = make_float2(v0, v1);
                *(float2*)&smf[S2B / 4 + (r + 8) * LDS2 + c] = make_float2(v2, v3);
            } else if (c < 176) {
                int cc = c - 128;
                *(float2*)&smf[GSB / 4 + r * LDGS + cc]       = make_float2(v0, v1);
                *(float2*)&smf[GSB / 4 + (r + 8) * LDGS + cc] = make_float2(v2, v3);
            }
        }
    __syncthreads();

    // ================= attention softmax: Y[r][i] = softmax_j(ph_i*th_j) . g ==========
    {
        int r = tid >> 2;                  // 0..63
        int i0 = (tid & 3) * 4;
        const float* srow = &smf[GSB / 4 + r * LDGS];
        float gg[16], th[16];
#pragma unroll
        for (int j = 0; j < 16; j++) { gg[j] = srow[j]; th[j] = srow[16 + j]; }
        float yv[4];
#pragma unroll
        for (int q = 0; q < 4; q++) {
            float ph = srow[32 + i0 + q];
            float m = ph * th[0];
#pragma unroll
            for (int j = 1; j < 16; j++) m = fmaxf(m, ph * th[j]);
            float s = 0.f, ys = 0.f;
#pragma unroll
            for (int j = 0; j < 16; j++) {
                float e = __expf(ph * th[j] - m);
                s += e; ys += e * gg[j];
            }
            yv[q] = ys / s;
        }
        uint2 h;
        h.x = packh(yv[0], yv[1]);
        h.y = packh(yv[2], yv[3]);
        *(uint2*)(smc + YHB + r * LDYBY + i0 * 2) = h;
    }
    CP_WAIT(0);        // wo fragments resident
    __syncthreads();

    // ================= GEMM3: OUT = Y @ wo + bo + H2 (residual), K=16 =================
    {
        const int row0g = (wid & 3) * 16;
        const int wn3   = wid >> 2;
        const int col0g = wn3 * 64;
        const uint4* Wf = (const uint4*)(smc + WOFB);
        float acc3[8][4];
#pragma unroll
        for (int nt = 0; nt < 8; nt++)
#pragma unroll
            for (int q = 0; q < 4; q++) acc3[nt][q] = 0.f;

        unsigned a[4];
        ldsm4(a, sbase + YHB + (row0g + (lane & 15)) * LDYBY + ((lane >> 4) << 4));
#pragma unroll
        for (int p = 0; p < 4; p++) {
            uint4 bv = Wf[(wn3 * 4 + p) * 32 + lane];
            mma16(acc3[2 * p],     a, bv.x, bv.y);
            mma16(acc3[2 * p + 1], a, bv.z, bv.w);
        }

#pragma unroll
        for (int nt = 0; nt < 8; nt++) {
            int r = row0g + (lane >> 2);
            int c = col0g + nt * 8 + (lane & 3) * 2;
            float bb0 = smf[BOBB / 4 + c], bb1 = smf[BOBB / 4 + c + 1];
            long e = e0 + r;
            if (e < E_TOTAL) {
                float o0 = acc3[nt][0] + smf[S2B / 4 + r * LDS2 + c] + bb0;
                float o1 = acc3[nt][1] + smf[S2B / 4 + r * LDS2 + c + 1] + bb1;
                *(float2*)&out[e * 128 + c] = make_float2(o0, o1);
            }
            long e2 = e + 8;
            if (e2 < E_TOTAL) {
                float o2 = acc3[nt][2] + smf[S2B / 4 + (r + 8) * LDS2 + c] + bb0;
                float o3 = acc3[nt][3] + smf[S2B / 4 + (r + 8) * LDS2 + c + 1] + bb1;
                *(float2*)&out[e2 * 128 + c] = make_float2(o2, o3);
            }
        }
    }
}

extern "C" void kernel_launch(void* const* d_in, const int* in_sizes, int n_in,
                              void* d_out, int out_size) {
    const float* src = (const float*)d_in[0];
    const float* tgt = (const float*)d_in[1];
    const float* ea  = (const float*)d_in[2];
    const float* w1  = (const float*)d_in[3];
    const float* b1  = (const float*)d_in[4];
    const float* w2  = (const float*)d_in[5];
    const float* b2  = (const float*)d_in[6];
    const float* wg  = (const float*)d_in[7];
    const float* bg  = (const float*)d_in[8];
    const float* wt  = (const float*)d_in[9];
    const float* bt  = (const float*)d_in[10];
    const float* wp  = (const float*)d_in[11];
    const float* bp  = (const float*)d_in[12];
    const float* wo  = (const float*)d_in[13];
    const float* bo  = (const float*)d_in[14];
    float* out = (float*)d_out;

    cudaFuncSetAttribute(edge_att_kernel,
                         cudaFuncAttributeMaxDynamicSharedMemorySize, SMEM_BYTES);

    prep_w2e<<<192, 128>>>(w2, b2, wg, bg, wt, bt, wp, bp);
    prep_w1f<<<48, 128>>>(w1);
    prep_w2f<<<24, 128>>>();
    prep_wof<<<2, 128>>>(wo);

    int grid = (E_TOTAL + TILE_M - 1) / TILE_M;   // 4688
    edge_att_kernel<<<grid, NTH, SMEM_BYTES>>>(src, tgt, ea, b1, bo, out);
}

// round 9
// speedup vs baseline: 2.2035x; 1.0191x over previous
#include <cuda_runtime.h>
#include <cuda_fp16.h>
#include <cstdint>

#define E_TOTAL 300000
#define TILE_M  64
#define NTH     256

// ---------------- shared memory byte offsets ----------------
#define A1B(s)   ((s) * 5120)               // 3 stages: 64 rows x 80B (32 fp16 + pad)
#define LDA1BY   80
#define B1B(s)   (15360 + (s) * 8192)       // 3 stages, end 39936
#define B2B(s)   (39936 + (s) * 12288)      // 4 stages (no reuse -> no ring race), end 89088
#define WOFB     89088                       // 4KB, end 93184
#define H1HB     93184                       // fp16 64 x 136 (272B rows), end 110592
#define LDHBY    272
#define S2B      93184                       // fp16 residual overlays H1h after GEMM2
#define LDS2BY   272
#define GSB      0                           // fp32 64 x 50 (overlay A ring, post-GEMM1)
#define LDGS     50
#define YHB      12800                       // fp16 64 x 24 (48B rows), overlays ring region
#define LDYBY    48
#define B1BB     110592                      // fp32 b1[128]
#define B2EB     111104                      // fp32 b2e[192]
#define BOBB     111872                      // fp32 bo[128]
#define SMEM_BYTES 112384                    // 2 CTAs/SM

// ---------------- device-global prepped weights (fp16 fragment order) ----------------
// GEMM1 B frags: [kc(12,k32)][ks(2)][wn(4)][p(2)][lane(32)] x uint4
__device__ __align__(16) unsigned g_w1f[6144 * 4];
// GEMM2 B frags: [kc(4,k32)][ks(2)][wn(4)][p(3)][lane(32)] x uint4
__device__ __align__(16) unsigned g_w2f[3072 * 4];
// GEMM3 wo frags: [wn(2)][p(4)][lane(32)] x uint4
__device__ __align__(16) unsigned g_wof[256 * 4];
__device__ float g_b2e[192];

// ---------------- helpers ----------------
__device__ __forceinline__ unsigned packh(float lo, float hi) {
    __half2 h = __halves2half2(__float2half_rn(lo), __float2half_rn(hi));
    return *(unsigned*)&h;
}
__device__ __forceinline__ uint32_t smem_u32(const void* p) {
    uint32_t a;
    asm("{ .reg .u64 t; cvta.to.shared.u64 t, %1; cvt.u32.u64 %0, t; }" : "=r"(a) : "l"(p));
    return a;
}
__device__ __forceinline__ void cp16(uint32_t s, const void* g) {
    asm volatile("cp.async.cg.shared.global [%0], [%1], 16;" :: "r"(s), "l"(g));
}
#define CP_COMMIT() asm volatile("cp.async.commit_group;" ::: "memory")
#define CP_WAIT(n)  asm volatile("cp.async.wait_group %0;" :: "n"(n) : "memory")

__device__ __forceinline__ void ldsm4(unsigned* d, uint32_t addr) {
    asm volatile("ldmatrix.sync.aligned.m8n8.x4.shared.b16 {%0,%1,%2,%3}, [%4];"
                 : "=r"(d[0]), "=r"(d[1]), "=r"(d[2]), "=r"(d[3]) : "r"(addr));
}
__device__ __forceinline__ void mma16(float* c, const unsigned* a, unsigned b0, unsigned b1) {
    asm volatile(
        "mma.sync.aligned.m16n8k16.row.col.f32.f16.f16.f32 "
        "{%0,%1,%2,%3}, {%4,%5,%6,%7}, {%8,%9}, {%0,%1,%2,%3};"
        : "+f"(c[0]), "+f"(c[1]), "+f"(c[2]), "+f"(c[3])
        : "r"(a[0]), "r"(a[1]), "r"(a[2]), "r"(a[3]), "r"(b0), "r"(b1));
}

// ---------------- single prep kernel (keeps launch count low for ncu) ----------------
__device__ float w2e_at(int n, int k, const float* w2,
                        const float* wg, const float* wt, const float* wp) {
    if (n < 128) return w2[k * 128 + n];
    if (n >= 176) return 0.f;
    int p = (n - 128) >> 4, j = (n - 128) & 15;
    const float* W = (p == 0) ? wg : (p == 1) ? wt : wp;
    float s = 0.f;
    for (int m = 0; m < 128; m++) s += w2[k * 128 + m] * W[m * 16 + j];
    return s;
}

#define W1F_N 6144
#define W2F_N 3072
#define WOF_N 256
#define B2E_N 192

__global__ void prep_all(const float* __restrict__ w1, const float* __restrict__ w2,
                         const float* __restrict__ b2,
                         const float* __restrict__ wg, const float* __restrict__ bg,
                         const float* __restrict__ wt, const float* __restrict__ bt,
                         const float* __restrict__ wp, const float* __restrict__ bp,
                         const float* __restrict__ wo) {
    int gid = blockIdx.x * 128 + threadIdx.x;
    if (gid < W1F_N) {
        int u = gid, lane = u & 31, r = u >> 5;
        int p  = r & 1;
        int wn = (r >> 1) & 3;
        int ks = (r >> 3) & 1;
        int kc = r >> 4;                       // 0..11
        int n0 = wn * 32 + p * 16 + (lane >> 2);
        int kb = kc * 32 + ks * 16 + 2 * (lane & 3);
        unsigned* o = g_w1f + u * 4;
        o[0] = packh(w1[kb * 128 + n0],       w1[(kb + 1) * 128 + n0]);
        o[1] = packh(w1[(kb + 8) * 128 + n0], w1[(kb + 9) * 128 + n0]);
        o[2] = packh(w1[kb * 128 + n0 + 8],       w1[(kb + 1) * 128 + n0 + 8]);
        o[3] = packh(w1[(kb + 8) * 128 + n0 + 8], w1[(kb + 9) * 128 + n0 + 8]);
    } else if (gid < W1F_N + W2F_N) {
        int u = gid - W1F_N, lane = u & 31, r = u >> 5;   // 0..95
        int p = r % 3; r /= 3;                             // 0..31
        int wn = r & 3;
        int ks = (r >> 2) & 1;
        int kc = r >> 3;                                   // 0..3
        int n0 = wn * 48 + p * 16 + (lane >> 2);
        int kb = kc * 32 + ks * 16 + 2 * (lane & 3);
        unsigned* o = g_w2f + u * 4;
        o[0] = packh(w2e_at(n0, kb, w2, wg, wt, wp),     w2e_at(n0, kb + 1, w2, wg, wt, wp));
        o[1] = packh(w2e_at(n0, kb + 8, w2, wg, wt, wp), w2e_at(n0, kb + 9, w2, wg, wt, wp));
        o[2] = packh(w2e_at(n0 + 8, kb, w2, wg, wt, wp),     w2e_at(n0 + 8, kb + 1, w2, wg, wt, wp));
        o[3] = packh(w2e_at(n0 + 8, kb + 8, w2, wg, wt, wp), w2e_at(n0 + 8, kb + 9, w2, wg, wt, wp));
    } else if (gid < W1F_N + W2F_N + WOF_N) {
        int u = gid - W1F_N - W2F_N, lane = u & 31, r = u >> 5;  // 0..7
        int p  = r & 3;
        int wn = r >> 2;
        int n0 = wn * 64 + p * 16 + (lane >> 2);
        int kb = 2 * (lane & 3);
        unsigned* o = g_wof + u * 4;
        o[0] = packh(wo[kb * 128 + n0],       wo[(kb + 1) * 128 + n0]);
        o[1] = packh(wo[(kb + 8) * 128 + n0], wo[(kb + 9) * 128 + n0]);
        o[2] = packh(wo[kb * 128 + n0 + 8],       wo[(kb + 1) * 128 + n0 + 8]);
        o[3] = packh(wo[(kb + 8) * 128 + n0 + 8], wo[(kb + 9) * 128 + n0 + 8]);
    } else if (gid < W1F_N + W2F_N + WOF_N + B2E_N) {
        int n = gid - W1F_N - W2F_N - WOF_N;               // 0..191
        float b = 0.f;
        if (n < 128) b = b2[n];
        else if (n < 176) {
            int p = (n - 128) >> 4, j = (n - 128) & 15;
            const float* W = (p == 0) ? wg : (p == 1) ? wt : wp;
            const float* B = (p == 0) ? bg : (p == 1) ? bt : bp;
            b = B[j];
            for (int m = 0; m < 128; m++) b += b2[m] * W[m * 16 + j];
        }
        g_b2e[n] = b;
    }
}

// ---------------- main fused kernel: 64 edges/CTA, 256 threads, 2 CTA/SM ----------------
extern __shared__ char smc[];

__global__ void __launch_bounds__(NTH, 2)
edge_att_kernel(const float* __restrict__ src, const float* __restrict__ tgt,
                const float* __restrict__ ea,
                const float* __restrict__ b1v, const float* __restrict__ bo,
                float* __restrict__ out) {
    const int tid  = threadIdx.x;
    const int lane = tid & 31;
    const int wid  = tid >> 5;       // 8 warps
    const int wm   = wid & 1;        // 2 M-warps (32 rows each)
    const int wn   = wid >> 1;       // 4 N-warps
    const int row0 = wm * 32;
    const long e0  = (long)blockIdx.x * TILE_M;
    const uint32_t sbase = smem_u32(smc);
    float* smf = (float*)smc;

    // persistent biases (fp32)
    if (tid < 128) smf[B1BB / 4 + tid] = b1v[tid];
    if (tid < 128) smf[BOBB / 4 + tid] = bo[tid];
    if (tid < 192) smf[B2EB / 4 + tid] = g_b2e[tid];

    // ---- staging lambdas ----
    auto ldgA = [&](int kc, float4* pr) {     // k32 chunk: 64 rows x 32 fp32
        const float* sp = (kc < 4) ? src : (kc < 8) ? tgt : ea;
        int cin = (kc & 3) * 32;
#pragma unroll
        for (int i = 0; i < 2; i++) {
            int f = tid + i * NTH;            // 0..511
            int r = f >> 3, c4 = f & 7;
            long e = e0 + r; if (e >= E_TOTAL) e = E_TOTAL - 1;
            pr[i] = *(const float4*)(sp + e * 128 + cin + c4 * 4);
        }
    };
    auto stsA = [&](int kc, const float4* pr) {
        char* base = smc + A1B(kc % 3);
#pragma unroll
        for (int i = 0; i < 2; i++) {
            int f = tid + i * NTH;
            int r = f >> 3, c4 = f & 7;
            uint2 h;
            h.x = packh(pr[i].x, pr[i].y);
            h.y = packh(pr[i].z, pr[i].w);
            *(uint2*)(base + r * LDA1BY + c4 * 8) = h;
        }
    };
    auto cpB1 = [&](int kc) {                 // 512 uint4 = 8KB
        uint32_t sb = sbase + B1B(kc % 3);
#pragma unroll
        for (int i = 0; i < 2; i++) {
            int f = tid + i * NTH;
            cp16(sb + f * 16, g_w1f + (kc * 512 + f) * 4);
        }
    };
    auto cpB2 = [&](int kc) {                 // 768 uint4 = 12KB, dedicated stage per chunk
        uint32_t sb = sbase + B2B(kc);
#pragma unroll
        for (int i = 0; i < 3; i++) {
            int f = tid + i * NTH;
            cp16(sb + f * 16, g_w2f + (kc * 768 + f) * 4);
        }
    };
    auto cpWOF = [&]() {
        cp16(sbase + WOFB + tid * 16, g_wof + tid * 4);
    };

    // ================= GEMM1: H1 = relu(X @ w1 + b1), K=384 (12 x k32) ================
    float acc1[2][4][4];
#pragma unroll
    for (int mt = 0; mt < 2; mt++)
#pragma unroll
        for (int nt = 0; nt < 4; nt++)
#pragma unroll
            for (int q = 0; q < 4; q++) acc1[mt][nt][q] = 0.f;

    float4 pa[2][2];
    ldgA(0, pa[0]); stsA(0, pa[0]);
    ldgA(1, pa[1]);
    cpB1(0); CP_COMMIT();
    cpB1(1); CP_COMMIT();

#pragma unroll
    for (int kc = 0; kc < 12; kc++) {
        CP_WAIT(1);
        __syncthreads();
        // one commit group per iteration; GEMM2/GEMM3 weights ride the tail groups
        if (kc + 2 < 12) cpB1(kc + 2);
        if (kc == 9)  { cpB2(0); cpB2(1); }
        if (kc == 10) { cpB2(2); cpWOF(); }
        if (kc == 11) { cpB2(3); }
        CP_COMMIT();

        const uint32_t Ab = sbase + A1B(kc % 3);
        const uint4* Bb = (const uint4*)(smc + B1B(kc % 3));
#pragma unroll
        for (int ks = 0; ks < 2; ks++) {
            unsigned a0[4], a1[4];
            uint32_t ab = Ab + (row0 + (lane & 15)) * LDA1BY + ((lane >> 4) << 4) + ks * 32;
            ldsm4(a0, ab);
            ldsm4(a1, ab + 16 * LDA1BY);
#pragma unroll
            for (int p = 0; p < 2; p++) {
                uint4 bv = Bb[(ks * 8 + wn * 2 + p) * 32 + lane];
                mma16(acc1[0][2 * p],     a0, bv.x, bv.y);
                mma16(acc1[0][2 * p + 1], a0, bv.z, bv.w);
                mma16(acc1[1][2 * p],     a1, bv.x, bv.y);
                mma16(acc1[1][2 * p + 1], a1, bv.z, bv.w);
            }
        }
        if (kc + 1 < 12) stsA(kc + 1, pa[(kc + 1) & 1]);
        if (kc + 2 < 12) ldgA(kc + 2, pa[kc & 1]);
    }

    // ---- epilogue 1: H1h = fp16(relu(acc + b1)), stride 272B (conflict-free) ----
    {
        const int col0 = wn * 32;
#pragma unroll
        for (int mt = 0; mt < 2; mt++)
#pragma unroll
            for (int nt = 0; nt < 4; nt++) {
                int r = row0 + mt * 16 + (lane >> 2);
                int c = col0 + nt * 8 + (lane & 3) * 2;
                float bb0 = smf[B1BB / 4 + c], bb1 = smf[B1BB / 4 + c + 1];
                *(unsigned*)(smc + H1HB + r * LDHBY + c * 2) =
                    packh(fmaxf(acc1[mt][nt][0] + bb0, 0.f), fmaxf(acc1[mt][nt][1] + bb1, 0.f));
                *(unsigned*)(smc + H1HB + (r + 8) * LDHBY + c * 2) =
                    packh(fmaxf(acc1[mt][nt][2] + bb0, 0.f), fmaxf(acc1[mt][nt][3] + bb1, 0.f));
            }
    }
    __syncthreads();   // H1h visible

    // ================= GEMM2: [H2|G|TH|PH|pad] = H1 @ w2ext, N=192, K=128 =============
    // 4 x k32 chunks, DEDICATED stages (prefetched during GEMM1) -> barrier-free interior
    float acc2[2][6][4];
#pragma unroll
    for (int mt = 0; mt < 2; mt++)
#pragma unroll
        for (int nt = 0; nt < 6; nt++)
#pragma unroll
            for (int q = 0; q < 4; q++) acc2[mt][nt][q] = 0.f;

#pragma unroll
    for (int kc = 0; kc < 4; kc++) {
        if (kc == 0) CP_WAIT(2);      // B2(0),B2(1) groups done (pending: kc10,kc11 groups)
        if (kc == 2) CP_WAIT(1);      // B2(2)+WOF done
        if (kc == 3) CP_WAIT(0);      // B2(3) done

        const uint4* Bb = (const uint4*)(smc + B2B(kc));
#pragma unroll
        for (int ks = 0; ks < 2; ks++) {
            unsigned a0[4], a1[4];
            uint32_t ab = sbase + H1HB + (row0 + (lane & 15)) * LDHBY +
                          ((lane >> 4) << 4) + kc * 64 + ks * 32;
            ldsm4(a0, ab);
            ldsm4(a1, ab + 16 * LDHBY);
#pragma unroll
            for (int p = 0; p < 3; p++) {
                uint4 bv = Bb[(ks * 12 + wn * 3 + p) * 32 + lane];
                mma16(acc2[0][2 * p],     a0, bv.x, bv.y);
                mma16(acc2[0][2 * p + 1], a0, bv.z, bv.w);
                mma16(acc2[1][2 * p],     a1, bv.x, bv.y);
                mma16(acc2[1][2 * p + 1], a1, bv.z, bv.w);
            }
        }
    }
    __syncthreads();   // all H1h reads done -> safe to overlay S2h

    // ---- epilogue 2: S2h fp16 (cols<128, overlays H1h); GS fp32 (128..175) ----
#pragma unroll
    for (int mt = 0; mt < 2; mt++)
#pragma unroll
        for (int nt = 0; nt < 6; nt++) {
            int r = row0 + mt * 16 + (lane >> 2);
            int c = wn * 48 + nt * 8 + (lane & 3) * 2;
            float bb0 = smf[B2EB / 4 + c], bb1 = smf[B2EB / 4 + c + 1];
            float v0 = acc2[mt][nt][0] + bb0, v1 = acc2[mt][nt][1] + bb1;
            float v2 = acc2[mt][nt][2] + bb0, v3 = acc2[mt][nt][3] + bb1;
            if (c < 128) {
                *(unsigned*)(smc + S2B + r * LDS2BY + c * 2)       = packh(v0, v1);
                *(unsigned*)(smc + S2B + (r + 8) * LDS2BY + c * 2) = packh(v2, v3);
            } else if (c < 176) {
                int cc = c - 128;
                *(float2*)&smf[GSB / 4 + r * LDGS + cc]       = make_float2(v0, v1);
                *(float2*)&smf[GSB / 4 + (r + 8) * LDGS + cc] = make_float2(v2, v3);
            }
        }
    __syncthreads();

    // ================= attention softmax: Y[r][i] = softmax_j(ph_i*th_j) . g ==========
    {
        int r = tid >> 2;                  // 0..63
        int i0 = (tid & 3) * 4;
        const float* srow = &smf[GSB / 4 + r * LDGS];
        float gg[16], th[16];
#pragma unroll
        for (int j = 0; j < 16; j++) { gg[j] = srow[j]; th[j] = srow[16 + j]; }
        float yv[4];
#pragma unroll
        for (int q = 0; q < 4; q++) {
            float ph = srow[32 + i0 + q];
            float m = ph * th[0];
#pragma unroll
            for (int j = 1; j < 16; j++) m = fmaxf(m, ph * th[j]);
            float s = 0.f, ys = 0.f;
#pragma unroll
            for (int j = 0; j < 16; j++) {
                float e = __expf(ph * th[j] - m);
                s += e; ys += e * gg[j];
            }
            yv[q] = ys / s;
        }
        uint2 h;
        h.x = packh(yv[0], yv[1]);
        h.y = packh(yv[2], yv[3]);
        *(uint2*)(smc + YHB + r * LDYBY + i0 * 2) = h;
    }
    __syncthreads();

    // ================= GEMM3: OUT = Y @ wo + bo + H2 (residual), K=16 =================
    {
        const int row0g = (wid & 3) * 16;
        const int wn3   = wid >> 2;
        const int col0g = wn3 * 64;
        const uint4* Wf = (const uint4*)(smc + WOFB);
        float acc3[8][4];
#pragma unroll
        for (int nt = 0; nt < 8; nt++)
#pragma unroll
            for (int q = 0; q < 4; q++) acc3[nt][q] = 0.f;

        unsigned a[4];
        ldsm4(a, sbase + YHB + (row0g + (lane & 15)) * LDYBY + ((lane >> 4) << 4));
#pragma unroll
        for (int p = 0; p < 4; p++) {
            uint4 bv = Wf[(wn3 * 4 + p) * 32 + lane];
            mma16(acc3[2 * p],     a, bv.x, bv.y);
            mma16(acc3[2 * p + 1], a, bv.z, bv.w);
        }

#pragma unroll
        for (int nt = 0; nt < 8; nt++) {
            int r = row0g + (lane >> 2);
            int c = col0g + nt * 8 + (lane & 3) * 2;
            float bb0 = smf[BOBB / 4 + c], bb1 = smf[BOBB / 4 + c + 1];
            long e = e0 + r;
            if (e < E_TOTAL) {
                __half2 s2 = *(__half2*)(smc + S2B + r * LDS2BY + c * 2);
                float o0 = acc3[nt][0] + __low2float(s2)  + bb0;
                float o1 = acc3[nt][1] + __high2float(s2) + bb1;
                *(float2*)&out[e * 128 + c] = make_float2(o0, o1);
            }
            long e2 = e + 8;
            if (e2 < E_TOTAL) {
                __half2 s2 = *(__half2*)(smc + S2B + (r + 8) * LDS2BY + c * 2);
                float o2 = acc3[nt][2] + __low2float(s2)  + bb0;
                float o3 = acc3[nt][3] + __high2float(s2) + bb1;
                *(float2*)&out[e2 * 128 + c] = make_float2(o2, o3);
            }
        }
    }
}

extern "C" void kernel_launch(void* const* d_in, const int* in_sizes, int n_in,
                              void* d_out, int out_size) {
    const float* src = (const float*)d_in[0];
    const float* tgt = (const float*)d_in[1];
    const float* ea  = (const float*)d_in[2];
    const float* w1  = (const float*)d_in[3];
    const float* b1  = (const float*)d_in[4];
    const float* w2  = (const float*)d_in[5];
    const float* b2  = (const float*)d_in[6];
    const float* wg  = (const float*)d_in[7];
    const float* bg  = (const float*)d_in[8];
    const float* wt  = (const float*)d_in[9];
    const float* bt  = (const float*)d_in[10];
    const float* wp  = (const float*)d_in[11];
    const float* bp  = (const float*)d_in[12];
    const float* wo  = (const float*)d_in[13];
    const float* bo  = (const float*)d_in[14];
    float* out = (float*)d_out;

    cudaFuncSetAttribute(edge_att_kernel,
                         cudaFuncAttributeMaxDynamicSharedMemorySize, SMEM_BYTES);

    prep_all<<<76, 128>>>(w1, w2, b2, wg, bg, wt, bt, wp, bp, wo);

    int grid = (E_TOTAL + TILE_M - 1) / TILE_M;   // 4688
    edge_att_kernel<<<grid, NTH, SMEM_BYTES>>>(src, tgt, ea, b1, bo, out);
}

// round 10
// speedup vs baseline: 2.5310x; 1.1486x over previous
#include <cuda_runtime.h>
#include <cuda_fp16.h>
#include <cstdint>

#define E_TOTAL 300000
#define TILE_M  64
#define NTH     256

// ---------------- shared memory byte offsets ----------------
#define A1B(s)   ((s) * 5120)               // 3 stages: 64 rows x 80B (32 fp16 + pad)
#define LDA1BY   80
#define GSB      0                           // fp32 64 x 50, overlays A ring post-GEMM1
#define LDGS     50
#define YHB      15360                       // fp16 64 x 24 (48B rows)
#define LDYBY    48
#define H1HB     18432                       // fp16 64 x 136 (272B rows)
#define LDHBY    272
#define S2B      18432                       // fp16 residual overlays H1h after GEMM2
#define LDS2BY   272
#define B1BB     35840                       // fp32 b1[128]
#define B2EB     36352                       // fp32 b2e[192]
#define BOBB     37120                       // fp32 bo[128]
#define SMEM_BYTES 37632                     // 2 CTAs/SM (reg-limited); L1D keeps ~150KB

// ---------------- device-global prepped weights (fp16, per-warp fragment order) ------
// GEMM1 B frags: [kc(12)][wn(4)][q(4: ks*2+p)][lane(32)] x uint4
__device__ __align__(16) unsigned g_w1f[6144 * 4];
// GEMM2 B frags: [kc(4)][wn(4)][q(6: ks*3+p)][lane(32)] x uint4
__device__ __align__(16) unsigned g_w2f[3072 * 4];
// GEMM3 wo frags: [wn(2)][p(4)][lane(32)] x uint4
__device__ __align__(16) unsigned g_wof[256 * 4];
__device__ float g_b2e[192];

// ---------------- helpers ----------------
__device__ __forceinline__ unsigned packh(float lo, float hi) {
    __half2 h = __halves2half2(__float2half_rn(lo), __float2half_rn(hi));
    return *(unsigned*)&h;
}
__device__ __forceinline__ uint32_t smem_u32(const void* p) {
    uint32_t a;
    asm("{ .reg .u64 t; cvta.to.shared.u64 t, %1; cvt.u32.u64 %0, t; }" : "=r"(a) : "l"(p));
    return a;
}
__device__ __forceinline__ void ldsm4(unsigned* d, uint32_t addr) {
    asm volatile("ldmatrix.sync.aligned.m8n8.x4.shared.b16 {%0,%1,%2,%3}, [%4];"
                 : "=r"(d[0]), "=r"(d[1]), "=r"(d[2]), "=r"(d[3]) : "r"(addr));
}
__device__ __forceinline__ void mma16(float* c, const unsigned* a, unsigned b0, unsigned b1) {
    asm volatile(
        "mma.sync.aligned.m16n8k16.row.col.f32.f16.f16.f32 "
        "{%0,%1,%2,%3}, {%4,%5,%6,%7}, {%8,%9}, {%0,%1,%2,%3};"
        : "+f"(c[0]), "+f"(c[1]), "+f"(c[2]), "+f"(c[3])
        : "r"(a[0]), "r"(a[1]), "r"(a[2]), "r"(a[3]), "r"(b0), "r"(b1));
}

// ---------------- single prep kernel ----------------
__device__ float w2e_at(int n, int k, const float* w2,
                        const float* wg, const float* wt, const float* wp) {
    if (n < 128) return w2[k * 128 + n];
    if (n >= 176) return 0.f;
    int p = (n - 128) >> 4, j = (n - 128) & 15;
    const float* W = (p == 0) ? wg : (p == 1) ? wt : wp;
    float s = 0.f;
    for (int m = 0; m < 128; m++) s += w2[k * 128 + m] * W[m * 16 + j];
    return s;
}

#define W1F_N 6144
#define W2F_N 3072
#define WOF_N 256
#define B2E_N 192

__global__ void prep_all(const float* __restrict__ w1, const float* __restrict__ w2,
                         const float* __restrict__ b2,
                         const float* __restrict__ wg, const float* __restrict__ bg,
                         const float* __restrict__ wt, const float* __restrict__ bt,
                         const float* __restrict__ wp, const float* __restrict__ bp,
                         const float* __restrict__ wo) {
    int gid = blockIdx.x * 128 + threadIdx.x;
    if (gid < W1F_N) {
        int u = gid, lane = u & 31, r = u >> 5;           // r 0..191
        int q  = r & 3;
        int p  = q & 1;
        int ks = q >> 1;
        int wn = (r >> 2) & 3;
        int kc = r >> 4;                                   // 0..11
        int n0 = wn * 32 + p * 16 + (lane >> 2);
        int kb = kc * 32 + ks * 16 + 2 * (lane & 3);
        unsigned* o = g_w1f + u * 4;
        o[0] = packh(w1[kb * 128 + n0],       w1[(kb + 1) * 128 + n0]);
        o[1] = packh(w1[(kb + 8) * 128 + n0], w1[(kb + 9) * 128 + n0]);
        o[2] = packh(w1[kb * 128 + n0 + 8],       w1[(kb + 1) * 128 + n0 + 8]);
        o[3] = packh(w1[(kb + 8) * 128 + n0 + 8], w1[(kb + 9) * 128 + n0 + 8]);
    } else if (gid < W1F_N + W2F_N) {
        int u = gid - W1F_N, lane = u & 31, r = u >> 5;   // r 0..95
        int q  = r % 6;
        int ks = q / 3;
        int p  = q % 3;
        int wn = (r / 6) & 3;
        int kc = r / 24;                                   // 0..3
        int n0 = wn * 48 + p * 16 + (lane >> 2);
        int kb = kc * 32 + ks * 16 + 2 * (lane & 3);
        unsigned* o = g_w2f + u * 4;
        o[0] = packh(w2e_at(n0, kb, w2, wg, wt, wp),     w2e_at(n0, kb + 1, w2, wg, wt, wp));
        o[1] = packh(w2e_at(n0, kb + 8, w2, wg, wt, wp), w2e_at(n0, kb + 9, w2, wg, wt, wp));
        o[2] = packh(w2e_at(n0 + 8, kb, w2, wg, wt, wp),     w2e_at(n0 + 8, kb + 1, w2, wg, wt, wp));
        o[3] = packh(w2e_at(n0 + 8, kb + 8, w2, wg, wt, wp), w2e_at(n0 + 8, kb + 9, w2, wg, wt, wp));
    } else if (gid < W1F_N + W2F_N + WOF_N) {
        int u = gid - W1F_N - W2F_N, lane = u & 31, r = u >> 5;  // 0..7
        int p  = r & 3;
        int wn = r >> 2;
        int n0 = wn * 64 + p * 16 + (lane >> 2);
        int kb = 2 * (lane & 3);
        unsigned* o = g_wof + u * 4;
        o[0] = packh(wo[kb * 128 + n0],       wo[(kb + 1) * 128 + n0]);
        o[1] = packh(wo[(kb + 8) * 128 + n0], wo[(kb + 9) * 128 + n0]);
        o[2] = packh(wo[kb * 128 + n0 + 8],       wo[(kb + 1) * 128 + n0 + 8]);
        o[3] = packh(wo[(kb + 8) * 128 + n0 + 8], wo[(kb + 9) * 128 + n0 + 8]);
    } else if (gid < W1F_N + W2F_N + WOF_N + B2E_N) {
        int n = gid - W1F_N - W2F_N - WOF_N;
        float b = 0.f;
        if (n < 128) b = b2[n];
        else if (n < 176) {
            int p = (n - 128) >> 4, j = (n - 128) & 15;
            const float* W = (p == 0) ? wg : (p == 1) ? wt : wp;
            const float* B = (p == 0) ? bg : (p == 1) ? bt : bp;
            b = B[j];
            for (int m = 0; m < 128; m++) b += b2[m] * W[m * 16 + j];
        }
        g_b2e[n] = b;
    }
}

// ---------------- main fused kernel: 64 edges/CTA, 256 threads, 2 CTA/SM ----------------
extern __shared__ char smc[];

__global__ void __launch_bounds__(NTH, 2)
edge_att_kernel(const float* __restrict__ src, const float* __restrict__ tgt,
                const float* __restrict__ ea,
                const float* __restrict__ b1v, const float* __restrict__ bo,
                float* __restrict__ out) {
    const int tid  = threadIdx.x;
    const int lane = tid & 31;
    const int wid  = tid >> 5;       // 8 warps
    const int wm   = wid & 1;        // 2 M-warps (32 rows each)
    const int wn   = wid >> 1;       // 4 N-warps
    const int row0 = wm * 32;
    const long e0  = (long)blockIdx.x * TILE_M;
    const uint32_t sbase = smem_u32(smc);
    float* smf = (float*)smc;

    // persistent biases (fp32)
    if (tid < 128) smf[B1BB / 4 + tid] = b1v[tid];
    if (tid < 128) smf[BOBB / 4 + tid] = bo[tid];
    if (tid < 192) smf[B2EB / 4 + tid] = g_b2e[tid];

    // per-warp B fragment pointers (L2/L1D-resident prepped weights)
    const uint4* __restrict__ w1p = ((const uint4*)g_w1f) + wn * 128 + lane;  // +kc*512, +q*32
    const uint4* __restrict__ w2p = ((const uint4*)g_w2f) + wn * 192 + lane;  // +kc*768, +q*32

    // ---- A staging (LDG fp32 -> pack fp16 -> STS) ----
    auto ldgA = [&](int kc, float4* pr) {     // k32 chunk: 64 rows x 32 fp32
        const float* sp = (kc < 4) ? src : (kc < 8) ? tgt : ea;
        int cin = (kc & 3) * 32;
#pragma unroll
        for (int i = 0; i < 2; i++) {
            int f = tid + i * NTH;
            int r = f >> 3, c4 = f & 7;
            long e = e0 + r; if (e >= E_TOTAL) e = E_TOTAL - 1;
            pr[i] = *(const float4*)(sp + e * 128 + cin + c4 * 4);
        }
    };
    auto stsA = [&](int kc, const float4* pr) {
        char* base = smc + A1B(kc % 3);
#pragma unroll
        for (int i = 0; i < 2; i++) {
            int f = tid + i * NTH;
            int r = f >> 3, c4 = f & 7;
            uint2 h;
            h.x = packh(pr[i].x, pr[i].y);
            h.y = packh(pr[i].z, pr[i].w);
            *(uint2*)(base + r * LDA1BY + c4 * 8) = h;
        }
    };
    auto ldgB1 = [&](int kc, uint4* d) {
        const uint4* p = w1p + kc * 512;
#pragma unroll
        for (int q = 0; q < 4; q++) d[q] = p[q * 32];
    };
    auto ldgB2 = [&](int kc, uint4* d) {
        const uint4* p = w2p + kc * 768;
#pragma unroll
        for (int q = 0; q < 6; q++) d[q] = p[q * 32];
    };

    // ================= GEMM1: H1 = relu(X @ w1 + b1), K=384 (12 x k32) ================
    float acc1[2][4][4];
#pragma unroll
    for (int mt = 0; mt < 2; mt++)
#pragma unroll
        for (int nt = 0; nt < 4; nt++)
#pragma unroll
            for (int q = 0; q < 4; q++) acc1[mt][nt][q] = 0.f;

    float4 pa[2][2];
    uint4 bq[2][4];
    ldgA(0, pa[0]); stsA(0, pa[0]);
    ldgA(1, pa[1]);
    ldgB1(0, bq[0]);
    ldgB1(1, bq[1]);

#pragma unroll
    for (int kc = 0; kc < 12; kc++) {
        __syncthreads();               // A stage kc visible to all warps

        const uint32_t Ab = sbase + A1B(kc % 3);
#pragma unroll
        for (int ks = 0; ks < 2; ks++) {
            unsigned a0[4], a1[4];
            uint32_t ab = Ab + (row0 + (lane & 15)) * LDA1BY + ((lane >> 4) << 4) + ks * 32;
            ldsm4(a0, ab);
            ldsm4(a1, ab + 16 * LDA1BY);
#pragma unroll
            for (int p = 0; p < 2; p++) {
                uint4 bv = bq[kc & 1][ks * 2 + p];
                mma16(acc1[0][2 * p],     a0, bv.x, bv.y);
                mma16(acc1[0][2 * p + 1], a0, bv.z, bv.w);
                mma16(acc1[1][2 * p],     a1, bv.x, bv.y);
                mma16(acc1[1][2 * p + 1], a1, bv.z, bv.w);
            }
        }
        if (kc + 2 < 12) ldgB1(kc + 2, bq[kc & 1]);
        if (kc + 1 < 12) stsA(kc + 1, pa[(kc + 1) & 1]);
        if (kc + 2 < 12) ldgA(kc + 2, pa[kc & 1]);
    }

    // prefetch GEMM2 chunk 0 while epilogue runs
    uint4 bq2[2][6];
    ldgB2(0, bq2[0]);

    // ---- epilogue 1: H1h = fp16(relu(acc + b1)), stride 272B (conflict-free) ----
    {
        const int col0 = wn * 32;
#pragma unroll
        for (int mt = 0; mt < 2; mt++)
#pragma unroll
            for (int nt = 0; nt < 4; nt++) {
                int r = row0 + mt * 16 + (lane >> 2);
                int c = col0 + nt * 8 + (lane & 3) * 2;
                float bb0 = smf[B1BB / 4 + c], bb1 = smf[B1BB / 4 + c + 1];
                *(unsigned*)(smc + H1HB + r * LDHBY + c * 2) =
                    packh(fmaxf(acc1[mt][nt][0] + bb0, 0.f), fmaxf(acc1[mt][nt][1] + bb1, 0.f));
                *(unsigned*)(smc + H1HB + (r + 8) * LDHBY + c * 2) =
                    packh(fmaxf(acc1[mt][nt][2] + bb0, 0.f), fmaxf(acc1[mt][nt][3] + bb1, 0.f));
            }
    }
    ldgB2(1, bq2[1]);
    __syncthreads();   // H1h visible

    // ================= GEMM2: [H2|G|TH|PH|pad] = H1 @ w2ext, N=192, K=128 =============
    // 4 x k32 chunks, B in registers -> barrier-free interior
    float acc2[2][6][4];
#pragma unroll
    for (int mt = 0; mt < 2; mt++)
#pragma unroll
        for (int nt = 0; nt < 6; nt++)
#pragma unroll
            for (int q = 0; q < 4; q++) acc2[mt][nt][q] = 0.f;

#pragma unroll
    for (int kc = 0; kc < 4; kc++) {
#pragma unroll
        for (int ks = 0; ks < 2; ks++) {
            unsigned a0[4], a1[4];
            uint32_t ab = sbase + H1HB + (row0 + (lane & 15)) * LDHBY +
                          ((lane >> 4) << 4) + kc * 64 + ks * 32;
            ldsm4(a0, ab);
            ldsm4(a1, ab + 16 * LDHBY);
#pragma unroll
            for (int p = 0; p < 3; p++) {
                uint4 bv = bq2[kc & 1][ks * 3 + p];
                mma16(acc2[0][2 * p],     a0, bv.x, bv.y);
                mma16(acc2[0][2 * p + 1], a0, bv.z, bv.w);
                mma16(acc2[1][2 * p],     a1, bv.x, bv.y);
                mma16(acc2[1][2 * p + 1], a1, bv.z, bv.w);
            }
        }
        if (kc + 2 < 4) ldgB2(kc + 2, bq2[kc & 1]);
    }
    __syncthreads();   // all H1h reads done -> safe to overlay S2h

    // ---- epilogue 2: S2h fp16 (cols<128, overlays H1h); GS fp32 (128..175) ----
#pragma unroll
    for (int mt = 0; mt < 2; mt++)
#pragma unroll
        for (int nt = 0; nt < 6; nt++) {
            int r = row0 + mt * 16 + (lane >> 2);
            int c = wn * 48 + nt * 8 + (lane & 3) * 2;
            float bb0 = smf[B2EB / 4 + c], bb1 = smf[B2EB / 4 + c + 1];
            float v0 = acc2[mt][nt][0] + bb0, v1 = acc2[mt][nt][1] + bb1;
            float v2 = acc2[mt][nt][2] + bb0, v3 = acc2[mt][nt][3] + bb1;
            if (c < 128) {
                *(unsigned*)(smc + S2B + r * LDS2BY + c * 2)       = packh(v0, v1);
                *(unsigned*)(smc + S2B + (r + 8) * LDS2BY + c * 2) = packh(v2, v3);
            } else if (c < 176) {
                int cc = c - 128;
                *(float2*)&smf[GSB / 4 + r * LDGS + cc]       = make_float2(v0, v1);
                *(float2*)&smf[GSB / 4 + (r + 8) * LDGS + cc] = make_float2(v2, v3);
            }
        }
    __syncthreads();

    // GEMM3 wo fragments (LDG, latency hidden behind softmax)
    const int wn3 = wid >> 2;
    uint4 wq[4];
    {
        const uint4* wop = ((const uint4*)g_wof) + wn3 * 128 + lane;
#pragma unroll
        for (int p = 0; p < 4; p++) wq[p] = wop[p * 32];
    }

    // ================= attention softmax: Y[r][i] = softmax_j(ph_i*th_j) . g ==========
    {
        int r = tid >> 2;                  // 0..63
        int i0 = (tid & 3) * 4;
        const float* srow = &smf[GSB / 4 + r * LDGS];
        float gg[16], th[16];
#pragma unroll
        for (int j = 0; j < 16; j++) { gg[j] = srow[j]; th[j] = srow[16 + j]; }
        float yv[4];
#pragma unroll
        for (int q = 0; q < 4; q++) {
            float ph = srow[32 + i0 + q];
            float m = ph * th[0];
#pragma unroll
            for (int j = 1; j < 16; j++) m = fmaxf(m, ph * th[j]);
            float s = 0.f, ys = 0.f;
#pragma unroll
            for (int j = 0; j < 16; j++) {
                float e = __expf(ph * th[j] - m);
                s += e; ys += e * gg[j];
            }
            yv[q] = ys / s;
        }
        uint2 h;
        h.x = packh(yv[0], yv[1]);
        h.y = packh(yv[2], yv[3]);
        *(uint2*)(smc + YHB + r * LDYBY + i0 * 2) = h;
    }
    __syncthreads();

    // ================= GEMM3: OUT = Y @ wo + bo + H2 (residual), K=16 =================
    {
        const int row0g = (wid & 3) * 16;
        const int col0g = wn3 * 64;
        float acc3[8][4];
#pragma unroll
        for (int nt = 0; nt < 8; nt++)
#pragma unroll
            for (int q = 0; q < 4; q++) acc3[nt][q] = 0.f;

        unsigned a[4];
        ldsm4(a, sbase + YHB + (row0g + (lane & 15)) * LDYBY + ((lane >> 4) << 4));
#pragma unroll
        for (int p = 0; p < 4; p++) {
            mma16(acc3[2 * p],     a, wq[p].x, wq[p].y);
            mma16(acc3[2 * p + 1], a, wq[p].z, wq[p].w);
        }

#pragma unroll
        for (int nt = 0; nt < 8; nt++) {
            int r = row0g + (lane >> 2);
            int c = col0g + nt * 8 + (lane & 3) * 2;
            float bb0 = smf[BOBB / 4 + c], bb1 = smf[BOBB / 4 + c + 1];
            long e = e0 + r;
            if (e < E_TOTAL) {
                __half2 s2 = *(__half2*)(smc + S2B + r * LDS2BY + c * 2);
                float o0 = acc3[nt][0] + __low2float(s2)  + bb0;
                float o1 = acc3[nt][1] + __high2float(s2) + bb1;
                *(float2*)&out[e * 128 + c] = make_float2(o0, o1);
            }
            long e2 = e + 8;
            if (e2 < E_TOTAL) {
                __half2 s2 = *(__half2*)(smc + S2B + (r + 8) * LDS2BY + c * 2);
                float o2 = acc3[nt][2] + __low2float(s2)  + bb0;
                float o3 = acc3[nt][3] + __high2float(s2) + bb1;
                *(float2*)&out[e2 * 128 + c] = make_float2(o2, o3);
            }
        }
    }
}

extern "C" void kernel_launch(void* const* d_in, const int* in_sizes, int n_in,
                              void* d_out, int out_size) {
    const float* src = (const float*)d_in[0];
    const float* tgt = (const float*)d_in[1];
    const float* ea  = (const float*)d_in[2];
    const float* w1  = (const float*)d_in[3];
    const float* b1  = (const float*)d_in[4];
    const float* w2  = (const float*)d_in[5];
    const float* b2  = (const float*)d_in[6];
    const float* wg  = (const float*)d_in[7];
    const float* bg  = (const float*)d_in[8];
    const float* wt  = (const float*)d_in[9];
    const float* bt  = (const float*)d_in[10];
    const float* wp  = (const float*)d_in[11];
    const float* bp  = (const float*)d_in[12];
    const float* wo  = (const float*)d_in[13];
    const float* bo  = (const float*)d_in[14];
    float* out = (float*)d_out;

    cudaFuncSetAttribute(edge_att_kernel,
                         cudaFuncAttributeMaxDynamicSharedMemorySize, SMEM_BYTES);

    prep_all<<<76, 128>>>(w1, w2, b2, wg, bg, wt, bt, wp, bp, wo);

    int grid = (E_TOTAL + TILE_M - 1) / TILE_M;   // 4688
    edge_att_kernel<<<grid, NTH, SMEM_BYTES>>>(src, tgt, ea, b1, bo, out);
}